// round 13
// baseline (speedup 1.0000x reference)
#include <cuda_runtime.h>
#include <cuda_fp16.h>
#include <math.h>

// Problem constants
#define MROWS  50176
#define CDIM   384
#define HIDDEN 1536
#define NHEADS 12
#define HDIM   32
#define NWIN   49
#define BWIN   1024
#define KV_ELEMS (2 * 16 * NHEADS * NWIN * HDIM)   // 602112

typedef __half fp16;

// -------- scratch (device globals; no allocations allowed) --------
__device__ fp16 g_x1h[(size_t)MROWS * CDIM];
__device__ fp16 g_hw [(size_t)MROWS * CDIM];
__device__ fp16 g_qh [(size_t)MROWS * CDIM];
__device__ fp16 g_ao [(size_t)MROWS * CDIM];
__device__ fp16 g_h2 [(size_t)MROWS * CDIM];
__device__ fp16 g_mid[(size_t)MROWS * HIDDEN];
__device__ fp16 g_wq [384 * 384];
__device__ fp16 g_wp [384 * 384];
__device__ fp16 g_w1 [384 * 1536];
__device__ fp16 g_w2 [1536 * 384];
__device__ fp16 g_kvh[KV_ELEMS];
__device__ fp16 g_bmh[NHEADS * 50 * 50];   // fp16 bias matrix, pitch 50

// ================= PTX helpers =================
__device__ __forceinline__ unsigned smem_u32(const void* p) {
    unsigned a;
    asm("{ .reg .u64 t; cvta.to.shared.u64 t, %1; cvt.u32.u64 %0, t; }" : "=r"(a) : "l"(p));
    return a;
}
__device__ __forceinline__ void cp16(unsigned dst, const void* src) {
    asm volatile("cp.async.cg.shared.global [%0], [%1], 16;" :: "r"(dst), "l"(src) : "memory");
}
#define CP_COMMIT() asm volatile("cp.async.commit_group;" ::: "memory")
#define CP_WAIT(n)  asm volatile("cp.async.wait_group %0;" :: "n"(n) : "memory")

#define LDSM4(r, a)                                                                \
    asm volatile("ldmatrix.sync.aligned.m8n8.x4.shared.b16 {%0,%1,%2,%3}, [%4];"   \
        : "=r"((r)[0]), "=r"((r)[1]), "=r"((r)[2]), "=r"((r)[3]) : "r"(a))

#define LDSM4T(r, a)                                                               \
    asm volatile("ldmatrix.sync.aligned.m8n8.x4.trans.shared.b16 {%0,%1,%2,%3}, [%4];" \
        : "=r"((r)[0]), "=r"((r)[1]), "=r"((r)[2]), "=r"((r)[3]) : "r"(a))

#define MMA_F16(d, a, b0, b1)                                                      \
    asm volatile("mma.sync.aligned.m16n8k16.row.col.f32.f16.f16.f32 "              \
        "{%0,%1,%2,%3}, {%4,%5,%6,%7}, {%8,%9}, {%0,%1,%2,%3};"                    \
        : "+f"((d)[0]), "+f"((d)[1]), "+f"((d)[2]), "+f"((d)[3])                    \
        : "r"((a)[0]), "r"((a)[1]), "r"((a)[2]), "r"((a)[3]), "r"(b0), "r"(b1))

// ============================================================
// pre_kernel: LN1 (+window partition) fused with ALL conversions.
// ============================================================
#define WT_TILES 1440
#define KV_BLKS  588
#define BM_BLKS  226
#define PRE_GRID (MROWS + WT_TILES + KV_BLKS + BM_BLKS)

__global__ void pre_kernel(const float* __restrict__ x, const float* __restrict__ g,
                           const float* __restrict__ bb, fp16* __restrict__ oh,
                           const float* __restrict__ Wq, const float* __restrict__ Wp,
                           const float* __restrict__ W1, const float* __restrict__ W2,
                           const float* __restrict__ kv,
                           const int* __restrict__ rel, const float* __restrict__ btab,
                           fp16* __restrict__ oq, fp16* __restrict__ op,
                           fp16* __restrict__ o1, fp16* __restrict__ o2,
                           fp16* __restrict__ okv, fp16* __restrict__ bmh)
{
    __shared__ float tile[32][33];
    __shared__ float rs[4], rss[4], smean, sinv;

    int b = blockIdx.x;
    int tid = threadIdx.x;

    if (b < MROWS) {
        int w = b / NWIN, n = b % NWIN;
        int bimg = w >> 6, wy = (w >> 3) & 7, wx = w & 7;
        int iy = n / 7, ix = n % 7;
        size_t srow = (size_t)bimg * 3136 + (wy * 7 + iy) * 56 + (wx * 7 + ix);
        const float* xr = x + srow * CDIM;
        float v0 = xr[tid], v1 = xr[tid + 128], v2 = xr[tid + 256];
        float s = v0 + v1 + v2, ss = v0 * v0 + v1 * v1 + v2 * v2;
        #pragma unroll
        for (int o = 16; o; o >>= 1) {
            s  += __shfl_xor_sync(0xffffffffu, s,  o);
            ss += __shfl_xor_sync(0xffffffffu, ss, o);
        }
        int warp = tid >> 5, lane = tid & 31;
        if (lane == 0) { rs[warp] = s; rss[warp] = ss; }
        __syncthreads();
        if (tid == 0) {
            float S = rs[0] + rs[1] + rs[2] + rs[3];
            float SS = rss[0] + rss[1] + rss[2] + rss[3];
            float m = S * (1.0f / 384.0f);
            smean = m;
            sinv = rsqrtf(SS * (1.0f / 384.0f) - m * m + 1e-5f);
        }
        __syncthreads();
        size_t orow = (size_t)b * CDIM;
        #pragma unroll
        for (int c = 0; c < 3; ++c) {
            float vv = (c == 0 ? v0 : c == 1 ? v1 : v2);
            int col = tid + c * 128;
            oh[orow + col] = __float2half_rn((vv - smean) * sinv * g[col] + bb[col]);
        }
        return;
    }
    b -= MROWS;
    if (b < WT_TILES) {
        const float* W; fp16* o; int Kd, ld, tiles_n, tt;
        if (b < 144)      { W = Wq; o = oq; Kd = 384;  ld = 1152; tiles_n = 12; tt = b; }
        else if (b < 288) { W = Wp; o = op; Kd = 384;  ld = 384;  tiles_n = 12; tt = b - 144; }
        else if (b < 864) { W = W1; o = o1; Kd = 384;  ld = 1536; tiles_n = 48; tt = b - 288; }
        else              { W = W2; o = o2; Kd = 1536; ld = 384;  tiles_n = 12; tt = b - 864; }
        int tk = tt / tiles_n, tn = tt % tiles_n;
        int k0 = tk * 32, n0 = tn * 32;
        int tx = tid & 31, ty = tid >> 5;
        #pragma unroll
        for (int i = 0; i < 8; ++i)
            tile[ty + 4 * i][tx] = W[(size_t)(k0 + ty + 4 * i) * ld + n0 + tx];
        __syncthreads();
        #pragma unroll
        for (int i = 0; i < 8; ++i)
            o[(size_t)(n0 + ty + 4 * i) * Kd + k0 + tx] = __float2half_rn(tile[tx][ty + 4 * i]);
        return;
    }
    b -= WT_TILES;
    if (b < KV_BLKS) {
        int base = b * 1024 + tid;
        #pragma unroll
        for (int i = 0; i < 8; ++i) {
            int idx = base + i * 128;
            if (idx < KV_ELEMS) okv[idx] = __float2half_rn(kv[idx]);
        }
        return;
    }
    b -= KV_BLKS;
    {
        int t = b * 128 + tid;
        if (t < NHEADS * NWIN * NWIN) {
            int h = t / (NWIN * NWIN), ij = t % (NWIN * NWIN);
            int i = ij / NWIN, j = ij - i * NWIN;
            bmh[h * 2500 + i * 50 + j] = __float2half_rn(btab[rel[ij] * NHEADS + h]);
        }
    }
}

// ============================================================
// LayerNorm (fp16 input rows) -> fp16
// ============================================================
__global__ void ln_kernel_h(const fp16* __restrict__ xin, const float* __restrict__ g,
                            const float* __restrict__ bb, fp16* __restrict__ oh)
{
    int r = blockIdx.x;
    const fp16* xr = xin + (size_t)r * CDIM;
    int tid = threadIdx.x;
    float v0 = __half2float(xr[tid]);
    float v1 = __half2float(xr[tid + 128]);
    float v2 = __half2float(xr[tid + 256]);
    float s = v0 + v1 + v2, ss = v0 * v0 + v1 * v1 + v2 * v2;
    #pragma unroll
    for (int o = 16; o; o >>= 1) {
        s  += __shfl_xor_sync(0xffffffffu, s,  o);
        ss += __shfl_xor_sync(0xffffffffu, ss, o);
    }
    __shared__ float rs[4], rss[4], smean, sinv;
    int warp = tid >> 5, lane = tid & 31;
    if (lane == 0) { rs[warp] = s; rss[warp] = ss; }
    __syncthreads();
    if (tid == 0) {
        float S = rs[0] + rs[1] + rs[2] + rs[3];
        float SS = rss[0] + rss[1] + rss[2] + rss[3];
        float m = S * (1.0f / 384.0f);
        smean = m;
        sinv = rsqrtf(SS * (1.0f / 384.0f) - m * m + 1e-5f);
    }
    __syncthreads();
    size_t orow = (size_t)r * CDIM;
    #pragma unroll
    for (int c = 0; c < 3; ++c) {
        float vv = (c == 0 ? v0 : c == 1 ? v1 : v2);
        int col = tid + c * 128;
        oh[orow + col] = __float2half_rn((vv - smean) * sinv * g[col] + bb[col]);
    }
}

// ============================================================
// fp16 tensor-core GEMM: 128x128, KC=64, 3-stage cp.async.
// ============================================================
enum { EPI_Q = 0, EPI_PROJ = 1, EPI_GELU = 2, EPI_FC2 = 3 };
#define TILE_B   18432
#define STAGE_B  36864
#define NSTAGE   3
#define SMEM_DYN (NSTAGE * STAGE_B)   // 110592

template <int EPI>
__global__ void __launch_bounds__(256, 2)
mma_gemm(const fp16* __restrict__ Am, const fp16* __restrict__ Bm,
         int K, const float* __restrict__ bias,
         float* __restrict__ Cf, fp16* __restrict__ Ch,
         const float* __restrict__ resid, const fp16* __restrict__ residh,
         float scale)
{
    extern __shared__ char sm_raw[];
    unsigned sbase = smem_u32(sm_raw);

    int tid = threadIdx.x, wid = tid >> 5, lane = tid & 31;
    int bm = blockIdx.y * 128, bn = blockIdx.x * 128;
    int m0 = (wid & 3) * 32, n0 = (wid >> 2) * 64;

    int rowL[8], chL[8], tileL[8];
    #pragma unroll
    for (int t = 0; t < 8; ++t) {
        int item = tid + t * 256;
        tileL[t] = item >> 10;
        int rem = item & 1023;
        rowL[t] = rem >> 3; chL[t] = rem & 7;
    }

    auto load_stage = [&](int stage, int k0) {
        unsigned db = sbase + stage * STAGE_B;
        #pragma unroll
        for (int t = 0; t < 8; ++t) {
            const fp16* src = (tileL[t] ? Bm : Am)
                + (size_t)((tileL[t] ? bn : bm) + rowL[t]) * K + k0 + chL[t] * 8;
            cp16(db + tileL[t] * TILE_B + rowL[t] * 144 + chL[t] * 16, src);
        }
        CP_COMMIT();
    };

    float acc[2][8][4];
    #pragma unroll
    for (int a = 0; a < 2; ++a)
        #pragma unroll
        for (int b = 0; b < 8; ++b)
            #pragma unroll
            for (int c = 0; c < 4; ++c) acc[a][b][c] = 0.0f;

    int niter = K >> 6;
    load_stage(0, 0);
    load_stage(1, 64);

    unsigned a_base[2], b_base[4];
    #pragma unroll
    for (int mt = 0; mt < 2; ++mt)
        a_base[mt] = (m0 + mt * 16 + (lane & 15)) * 144 + (lane >> 4) * 16;
    #pragma unroll
    for (int nt = 0; nt < 4; ++nt)
        b_base[nt] = TILE_B + (n0 + nt * 16 + (lane & 15)) * 144 + (lane >> 4) * 16;

    int st = 0;
    for (int it = 0; it < niter; ++it) {
        CP_WAIT(1);
        __syncthreads();

        if (it + 2 < niter) {
            int pst = st + 2; if (pst >= 3) pst -= 3;
            load_stage(pst, (it + 2) * 64);
        } else CP_COMMIT();

        unsigned base = sbase + st * STAGE_B;

        #pragma unroll
        for (int kp = 0; kp < 2; ++kp) {
            unsigned koff = kp * 64;
            unsigned ah[2][2][4], bh[2][4][4];
            #pragma unroll
            for (int ks = 0; ks < 2; ++ks)
                #pragma unroll
                for (int mt = 0; mt < 2; ++mt)
                    LDSM4(ah[ks][mt], base + a_base[mt] + koff + ks * 32);
            #pragma unroll
            for (int ks = 0; ks < 2; ++ks)
                #pragma unroll
                for (int nt = 0; nt < 4; ++nt)
                    LDSM4(bh[ks][nt], base + b_base[nt] + koff + ks * 32);

            #pragma unroll
            for (int ks = 0; ks < 2; ++ks)
                #pragma unroll
                for (int nt = 0; nt < 4; ++nt)
                    #pragma unroll
                    for (int mt = 0; mt < 2; ++mt) {
                        MMA_F16(acc[mt][nt * 2 + 0], ah[ks][mt], bh[ks][nt][0], bh[ks][nt][2]);
                        MMA_F16(acc[mt][nt * 2 + 1], ah[ks][mt], bh[ks][nt][1], bh[ks][nt][3]);
                    }
        }
        if (++st >= 3) st = 0;
    }

    int r_in = lane >> 2, c_in = (lane & 3) * 2;
    #pragma unroll
    for (int mt = 0; mt < 2; ++mt) {
        #pragma unroll
        for (int j = 0; j < 8; ++j) {
            int col = bn + n0 + j * 8 + c_in;
            #pragma unroll
            for (int hf = 0; hf < 2; ++hf) {
                int row = bm + m0 + mt * 16 + r_in + hf * 8;
                float v0 = acc[mt][j][hf * 2 + 0];
                float v1 = acc[mt][j][hf * 2 + 1];
                if (EPI == EPI_Q) {
                    int w = row / NWIN, n = row % NWIN;
                    int hd = col >> 5, d = col & 31;
                    __half2 hp;
                    hp.x = __float2half_rn((v0 + bias[col]) * scale);
                    hp.y = __float2half_rn((v1 + bias[col + 1]) * scale);
                    *(__half2*)&Ch[((size_t)(w * NHEADS + hd) * NWIN + n) * HDIM + d] = hp;
                } else if (EPI == EPI_PROJ) {
                    int w = row / NWIN, n = row % NWIN;
                    int bimg = w >> 6, wy = (w >> 3) & 7, wx = w & 7;
                    int iy = n / 7, ix = n % 7;
                    size_t o = ((size_t)bimg * 3136 + (wy * 7 + iy) * 56 + (wx * 7 + ix)) * CDIM + col;
                    float2 r2 = *(const float2*)&resid[o];
                    __half2 hp;
                    hp.x = __float2half_rn(v0 + bias[col] + r2.x);
                    hp.y = __float2half_rn(v1 + bias[col + 1] + r2.y);
                    *(__half2*)&Ch[o] = hp;
                } else if (EPI == EPI_GELU) {
                    float a0 = v0 + bias[col], a1 = v1 + bias[col + 1];
                    float g0 = 0.5f * a0 * (1.0f + erff(a0 * 0.70710678118654752f));
                    float g1 = 0.5f * a1 * (1.0f + erff(a1 * 0.70710678118654752f));
                    __half2 hp;
                    hp.x = __float2half_rn(g0); hp.y = __float2half_rn(g1);
                    *(__half2*)&Ch[(size_t)row * HIDDEN + col] = hp;
                } else {
                    size_t o = (size_t)row * CDIM + col;
                    __half2 rh = *(const __half2*)&residh[o];
                    *(float2*)&Cf[o] = make_float2(v0 + bias[col] + __low2float(rh),
                                                   v1 + bias[col + 1] + __high2float(rh));
                }
            }
        }
    }
}

// ============================================================
// Tensor-core windowed attention, register softmax, 8-window
// batching: one block per (image, head, group-of-8-windows);
// k/v loaded into smem ONCE, reused for 8 q tiles.
// ============================================================
#define QK_PITCH 40
#define WBATCH   8

__global__ void __launch_bounds__(128)
attn_tc(const fp16* __restrict__ q, const fp16* __restrict__ kvh,
        const fp16* __restrict__ bmh, fp16* __restrict__ ao)
{
    __shared__ fp16 sq[64 * QK_PITCH];
    __shared__ fp16 sk[64 * QK_PITCH];
    __shared__ fp16 sv[64 * QK_PITCH];

    int g = blockIdx.x;
    int bh = g >> 3, wg = g & 7;          // bh = bimg*12 + h
    int bimg = bh / NHEADS, h = bh - bimg * NHEADS;
    int tid = threadIdx.x, wid = tid >> 5, lane = tid & 31;

    const fp16* kp = kvh + (size_t)bh * (NWIN * HDIM);
    const fp16* vp = kp + (size_t)16 * NHEADS * NWIN * HDIM;

    // ---- k, v: loaded once for all 8 windows ----
    for (int t = tid; t < 196; t += 128) {
        int row = t >> 2, col = (t & 3) * 8;
        *(uint4*)&sk[row * QK_PITCH + col] = ((const uint4*)kp)[t];
        *(uint4*)&sv[row * QK_PITCH + col] = ((const uint4*)vp)[t];
    }
    for (int t = tid; t < 60; t += 128) {   // zero-pad V k-rows 49..63
        int row = 49 + (t >> 2), col = (t & 3) * 8;
        *(uint4*)&sv[row * QK_PITCH + col] = make_uint4(0, 0, 0, 0);
    }

    unsigned sq_u = smem_u32(sq), sk_u = smem_u32(sk), sv_u = smem_u32(sv);
    int m0 = wid * 16;
    int r = lane >> 2, c2 = (lane & 3) * 2;
    int i1 = m0 + r, i2 = i1 + 8;
    const fp16* bp = bmh + h * 2500;

    for (int iw = 0; iw < WBATCH; ++iw) {
        int w = bimg * 64 + wg * 8 + iw;
        const fp16* qp = q + (size_t)(w * NHEADS + h) * (NWIN * HDIM);
        for (int t = tid; t < 196; t += 128) {
            int row = t >> 2, col = (t & 3) * 8;
            *(uint4*)&sq[row * QK_PITCH + col] = ((const uint4*)qp)[t];
        }
        __syncthreads();

        // ---- S = q @ k^T ----
        float acc[8][4];
        #pragma unroll
        for (int a = 0; a < 8; ++a)
            #pragma unroll
            for (int c = 0; c < 4; ++c) acc[a][c] = 0.0f;
        {
            unsigned ah[2][4], bh2[2][4][4];
            #pragma unroll
            for (int kt = 0; kt < 2; ++kt)
                LDSM4(ah[kt], sq_u + ((m0 + (lane & 15)) * QK_PITCH + kt * 16 + (lane >> 4) * 8) * 2);
            #pragma unroll
            for (int kt = 0; kt < 2; ++kt)
                #pragma unroll
                for (int nt = 0; nt < 4; ++nt)
                    LDSM4(bh2[kt][nt], sk_u + ((nt * 16 + (lane & 15)) * QK_PITCH + kt * 16 + (lane >> 4) * 8) * 2);
            #pragma unroll
            for (int kt = 0; kt < 2; ++kt)
                #pragma unroll
                for (int nt = 0; nt < 4; ++nt) {
                    MMA_F16(acc[nt * 2 + 0], ah[kt], bh2[kt][nt][0], bh2[kt][nt][2]);
                    MMA_F16(acc[nt * 2 + 1], ah[kt], bh2[kt][nt][1], bh2[kt][nt][3]);
                }
        }

        // ---- register softmax over rows i1, i2 ----
        float v1[16], v2[16];
        #pragma unroll
        for (int nj = 0; nj < 8; ++nj) {
            int j0 = nj * 8 + c2;
            float b0 = 0.f, b1 = 0.f, b2 = 0.f, b3 = 0.f;
            if (j0 < 49) {
                if (i1 < 49) {
                    __half2 bb = *(const __half2*)&bp[i1 * 50 + j0];
                    b0 = __low2float(bb); b1 = __high2float(bb);
                }
                if (i2 < 49) {
                    __half2 bb = *(const __half2*)&bp[i2 * 50 + j0];
                    b2 = __low2float(bb); b3 = __high2float(bb);
                }
            }
            v1[nj * 2 + 0] = (j0     < 49) ? acc[nj][0] + b0 : -1e30f;
            v1[nj * 2 + 1] = (j0 + 1 < 49) ? acc[nj][1] + b1 : -1e30f;
            v2[nj * 2 + 0] = (j0     < 49) ? acc[nj][2] + b2 : -1e30f;
            v2[nj * 2 + 1] = (j0 + 1 < 49) ? acc[nj][3] + b3 : -1e30f;
        }
        float m1 = -1e30f, m2 = -1e30f;
        #pragma unroll
        for (int t = 0; t < 16; ++t) { m1 = fmaxf(m1, v1[t]); m2 = fmaxf(m2, v2[t]); }
        m1 = fmaxf(m1, __shfl_xor_sync(0xffffffffu, m1, 1));
        m1 = fmaxf(m1, __shfl_xor_sync(0xffffffffu, m1, 2));
        m2 = fmaxf(m2, __shfl_xor_sync(0xffffffffu, m2, 1));
        m2 = fmaxf(m2, __shfl_xor_sync(0xffffffffu, m2, 2));
        float s1 = 0.f, s2 = 0.f;
        #pragma unroll
        for (int t = 0; t < 16; ++t) {
            v1[t] = __expf(v1[t] - m1); s1 += v1[t];
            v2[t] = __expf(v2[t] - m2); s2 += v2[t];
        }
        s1 += __shfl_xor_sync(0xffffffffu, s1, 1);
        s1 += __shfl_xor_sync(0xffffffffu, s1, 2);
        s2 += __shfl_xor_sync(0xffffffffu, s2, 1);
        s2 += __shfl_xor_sync(0xffffffffu, s2, 2);
        float inv1 = 1.0f / s1, inv2 = 1.0f / s2;

        // ---- pack P into MMA A-fragments ----
        unsigned pa[4][4];
        #pragma unroll
        for (int kt = 0; kt < 4; ++kt) {
            __half2 t0 = __floats2half2_rn(v1[4 * kt + 0] * inv1, v1[4 * kt + 1] * inv1);
            __half2 t1 = __floats2half2_rn(v2[4 * kt + 0] * inv2, v2[4 * kt + 1] * inv2);
            __half2 t2 = __floats2half2_rn(v1[4 * kt + 2] * inv1, v1[4 * kt + 3] * inv1);
            __half2 t3 = __floats2half2_rn(v2[4 * kt + 2] * inv2, v2[4 * kt + 3] * inv2);
            pa[kt][0] = *(unsigned*)&t0;
            pa[kt][1] = *(unsigned*)&t1;
            pa[kt][2] = *(unsigned*)&t2;
            pa[kt][3] = *(unsigned*)&t3;
        }

        // ---- O = P @ V (V row-major, trans ldmatrix) ----
        float oa[4][4];
        #pragma unroll
        for (int a = 0; a < 4; ++a)
            #pragma unroll
            for (int c = 0; c < 4; ++c) oa[a][c] = 0.0f;
        #pragma unroll
        for (int kt = 0; kt < 4; ++kt) {
            #pragma unroll
            for (int nt = 0; nt < 2; ++nt) {
                unsigned bh2[4];
                LDSM4T(bh2, sv_u + ((kt * 16 + (lane & 15)) * QK_PITCH + nt * 16 + (lane >> 4) * 8) * 2);
                MMA_F16(oa[nt * 2 + 0], pa[kt], bh2[0], bh2[1]);
                MMA_F16(oa[nt * 2 + 1], pa[kt], bh2[2], bh2[3]);
            }
        }
        #pragma unroll
        for (int nt = 0; nt < 4; ++nt) {
            int d = nt * 8 + c2;
            if (i1 < NWIN) {
                __half2 hp;
                hp.x = __float2half_rn(oa[nt][0]); hp.y = __float2half_rn(oa[nt][1]);
                *(__half2*)&ao[((size_t)w * NWIN + i1) * CDIM + h * HDIM + d] = hp;
            }
            if (i2 < NWIN) {
                __half2 hp;
                hp.x = __float2half_rn(oa[nt][2]); hp.y = __float2half_rn(oa[nt][3]);
                *(__half2*)&ao[((size_t)w * NWIN + i2) * CDIM + h * HDIM + d] = hp;
            }
        }
        __syncthreads();   // before next iteration overwrites sq
    }
}

// ============================================================
// launch
// ============================================================
extern "C" void kernel_launch(void* const* d_in, const int* in_sizes, int n_in,
                              void* d_out, int out_size)
{
    (void)in_sizes; (void)n_in; (void)out_size;
    const float* x     = (const float*)d_in[0];
    const float* kv    = (const float*)d_in[1];
    const int*   rel   = (const int*)d_in[2];
    const float* g1    = (const float*)d_in[5];
    const float* b1    = (const float*)d_in[6];
    const float* Wqkv  = (const float*)d_in[7];
    const float* bqkv  = (const float*)d_in[8];
    const float* btab  = (const float*)d_in[9];
    const float* Wproj = (const float*)d_in[10];
    const float* bproj = (const float*)d_in[11];
    const float* g2    = (const float*)d_in[12];
    const float* b2    = (const float*)d_in[13];
    const float* Wfc1  = (const float*)d_in[14];
    const float* bfc1  = (const float*)d_in[15];
    const float* Wfc2  = (const float*)d_in[16];
    const float* bfc2  = (const float*)d_in[17];
    float* out = (float*)d_out;

    static fp16 *x1h = nullptr;
    static fp16 *hw, *qh, *ao, *h2, *mid, *wq, *wp, *w1, *w2, *kvh, *bmh;
    if (!x1h) {
        cudaGetSymbolAddress((void**)&x1h, g_x1h);
        cudaGetSymbolAddress((void**)&bmh, g_bmh);
        cudaGetSymbolAddress((void**)&hw,  g_hw);
        cudaGetSymbolAddress((void**)&qh,  g_qh);
        cudaGetSymbolAddress((void**)&ao,  g_ao);
        cudaGetSymbolAddress((void**)&h2,  g_h2);
        cudaGetSymbolAddress((void**)&mid, g_mid);
        cudaGetSymbolAddress((void**)&wq,  g_wq);
        cudaGetSymbolAddress((void**)&wp,  g_wp);
        cudaGetSymbolAddress((void**)&w1,  g_w1);
        cudaGetSymbolAddress((void**)&w2,  g_w2);
        cudaGetSymbolAddress((void**)&kvh, g_kvh);
        cudaFuncSetAttribute(mma_gemm<EPI_Q>,    cudaFuncAttributeMaxDynamicSharedMemorySize, SMEM_DYN);
        cudaFuncSetAttribute(mma_gemm<EPI_PROJ>, cudaFuncAttributeMaxDynamicSharedMemorySize, SMEM_DYN);
        cudaFuncSetAttribute(mma_gemm<EPI_GELU>, cudaFuncAttributeMaxDynamicSharedMemorySize, SMEM_DYN);
        cudaFuncSetAttribute(mma_gemm<EPI_FC2>,  cudaFuncAttributeMaxDynamicSharedMemorySize, SMEM_DYN);
    }

    const float qscale = 0.17677669529663687f;

    pre_kernel<<<PRE_GRID, 128>>>(x, g1, b1, hw,
                                  Wqkv, Wproj, Wfc1, Wfc2, kv, rel, btab,
                                  wq, wp, w1, w2, kvh, bmh);

    mma_gemm<EPI_Q><<<dim3(3, 392), 256, SMEM_DYN>>>(hw, wq, 384,
        bqkv, nullptr, qh, nullptr, nullptr, qscale);

    // 16 images x 12 heads x 8 window-groups = 1536 blocks
    attn_tc<<<16 * NHEADS * 8, 128>>>(qh, kvh, bmh, ao);

    mma_gemm<EPI_PROJ><<<dim3(3, 392), 256, SMEM_DYN>>>(ao, wp, 384,
        bproj, nullptr, x1h, x, nullptr, 0.0f);

    ln_kernel_h<<<MROWS, 128>>>(x1h, g2, b2, h2);

    mma_gemm<EPI_GELU><<<dim3(12, 392), 256, SMEM_DYN>>>(h2, w1, 384,
        bfc1, nullptr, mid, nullptr, nullptr, 0.0f);

    mma_gemm<EPI_FC2><<<dim3(3, 392), 256, SMEM_DYN>>>(mid, w2, 1536,
        bfc2, out, nullptr, nullptr, x1h, 0.0f);
}

// round 14
// speedup vs baseline: 1.2857x; 1.2857x over previous
#include <cuda_runtime.h>
#include <cuda_fp16.h>
#include <math.h>

// Problem constants
#define MROWS  50176
#define CDIM   384
#define HIDDEN 1536
#define NHEADS 12
#define HDIM   32
#define NWIN   49
#define BWIN   1024
#define KV_ELEMS (2 * 16 * NHEADS * NWIN * HDIM)   // 602112

typedef __half fp16;

// -------- scratch (device globals; no allocations allowed) --------
__device__ fp16 g_x1h[(size_t)MROWS * CDIM];
__device__ fp16 g_hw [(size_t)MROWS * CDIM];
__device__ fp16 g_qh [(size_t)MROWS * CDIM];
__device__ fp16 g_ao [(size_t)MROWS * CDIM];
__device__ fp16 g_h2 [(size_t)MROWS * CDIM];
__device__ fp16 g_mid[(size_t)MROWS * HIDDEN];
__device__ fp16 g_wq [384 * 384];
__device__ fp16 g_wp [384 * 384];
__device__ fp16 g_w1 [384 * 1536];
__device__ fp16 g_w2 [1536 * 384];
__device__ fp16 g_kvh[KV_ELEMS];
__device__ fp16 g_bmh[NHEADS * 50 * 50];   // fp16 bias matrix, pitch 50

// ================= PTX helpers =================
__device__ __forceinline__ unsigned smem_u32(const void* p) {
    unsigned a;
    asm("{ .reg .u64 t; cvta.to.shared.u64 t, %1; cvt.u32.u64 %0, t; }" : "=r"(a) : "l"(p));
    return a;
}
__device__ __forceinline__ void cp16(unsigned dst, const void* src) {
    asm volatile("cp.async.cg.shared.global [%0], [%1], 16;" :: "r"(dst), "l"(src) : "memory");
}
#define CP_COMMIT() asm volatile("cp.async.commit_group;" ::: "memory")
#define CP_WAIT(n)  asm volatile("cp.async.wait_group %0;" :: "n"(n) : "memory")

#define LDSM4(r, a)                                                                \
    asm volatile("ldmatrix.sync.aligned.m8n8.x4.shared.b16 {%0,%1,%2,%3}, [%4];"   \
        : "=r"((r)[0]), "=r"((r)[1]), "=r"((r)[2]), "=r"((r)[3]) : "r"(a))

#define LDSM4T(r, a)                                                               \
    asm volatile("ldmatrix.sync.aligned.m8n8.x4.trans.shared.b16 {%0,%1,%2,%3}, [%4];" \
        : "=r"((r)[0]), "=r"((r)[1]), "=r"((r)[2]), "=r"((r)[3]) : "r"(a))

#define MMA_F16(d, a, b0, b1)                                                      \
    asm volatile("mma.sync.aligned.m16n8k16.row.col.f32.f16.f16.f32 "              \
        "{%0,%1,%2,%3}, {%4,%5,%6,%7}, {%8,%9}, {%0,%1,%2,%3};"                    \
        : "+f"((d)[0]), "+f"((d)[1]), "+f"((d)[2]), "+f"((d)[3])                    \
        : "r"((a)[0]), "r"((a)[1]), "r"((a)[2]), "r"((a)[3]), "r"(b0), "r"(b1))

// ============================================================
// pre_kernel: LN1 (+window partition) fused with ALL conversions.
// ============================================================
#define WT_TILES 1440
#define KV_BLKS  588
#define BM_BLKS  226
#define PRE_GRID (MROWS + WT_TILES + KV_BLKS + BM_BLKS)

__global__ void pre_kernel(const float* __restrict__ x, const float* __restrict__ g,
                           const float* __restrict__ bb, fp16* __restrict__ oh,
                           const float* __restrict__ Wq, const float* __restrict__ Wp,
                           const float* __restrict__ W1, const float* __restrict__ W2,
                           const float* __restrict__ kv,
                           const int* __restrict__ rel, const float* __restrict__ btab,
                           fp16* __restrict__ oq, fp16* __restrict__ op,
                           fp16* __restrict__ o1, fp16* __restrict__ o2,
                           fp16* __restrict__ okv, fp16* __restrict__ bmh)
{
    __shared__ float tile[32][33];
    __shared__ float rs[4], rss[4], smean, sinv;

    int b = blockIdx.x;
    int tid = threadIdx.x;

    if (b < MROWS) {
        int w = b / NWIN, n = b % NWIN;
        int bimg = w >> 6, wy = (w >> 3) & 7, wx = w & 7;
        int iy = n / 7, ix = n % 7;
        size_t srow = (size_t)bimg * 3136 + (wy * 7 + iy) * 56 + (wx * 7 + ix);
        const float* xr = x + srow * CDIM;
        float v0 = xr[tid], v1 = xr[tid + 128], v2 = xr[tid + 256];
        float s = v0 + v1 + v2, ss = v0 * v0 + v1 * v1 + v2 * v2;
        #pragma unroll
        for (int o = 16; o; o >>= 1) {
            s  += __shfl_xor_sync(0xffffffffu, s,  o);
            ss += __shfl_xor_sync(0xffffffffu, ss, o);
        }
        int warp = tid >> 5, lane = tid & 31;
        if (lane == 0) { rs[warp] = s; rss[warp] = ss; }
        __syncthreads();
        if (tid == 0) {
            float S = rs[0] + rs[1] + rs[2] + rs[3];
            float SS = rss[0] + rss[1] + rss[2] + rss[3];
            float m = S * (1.0f / 384.0f);
            smean = m;
            sinv = rsqrtf(SS * (1.0f / 384.0f) - m * m + 1e-5f);
        }
        __syncthreads();
        size_t orow = (size_t)b * CDIM;
        #pragma unroll
        for (int c = 0; c < 3; ++c) {
            float vv = (c == 0 ? v0 : c == 1 ? v1 : v2);
            int col = tid + c * 128;
            oh[orow + col] = __float2half_rn((vv - smean) * sinv * g[col] + bb[col]);
        }
        return;
    }
    b -= MROWS;
    if (b < WT_TILES) {
        const float* W; fp16* o; int Kd, ld, tiles_n, tt;
        if (b < 144)      { W = Wq; o = oq; Kd = 384;  ld = 1152; tiles_n = 12; tt = b; }
        else if (b < 288) { W = Wp; o = op; Kd = 384;  ld = 384;  tiles_n = 12; tt = b - 144; }
        else if (b < 864) { W = W1; o = o1; Kd = 384;  ld = 1536; tiles_n = 48; tt = b - 288; }
        else              { W = W2; o = o2; Kd = 1536; ld = 384;  tiles_n = 12; tt = b - 864; }
        int tk = tt / tiles_n, tn = tt % tiles_n;
        int k0 = tk * 32, n0 = tn * 32;
        int tx = tid & 31, ty = tid >> 5;
        #pragma unroll
        for (int i = 0; i < 8; ++i)
            tile[ty + 4 * i][tx] = W[(size_t)(k0 + ty + 4 * i) * ld + n0 + tx];
        __syncthreads();
        #pragma unroll
        for (int i = 0; i < 8; ++i)
            o[(size_t)(n0 + ty + 4 * i) * Kd + k0 + tx] = __float2half_rn(tile[tx][ty + 4 * i]);
        return;
    }
    b -= WT_TILES;
    if (b < KV_BLKS) {
        int base = b * 1024 + tid;
        #pragma unroll
        for (int i = 0; i < 8; ++i) {
            int idx = base + i * 128;
            if (idx < KV_ELEMS) okv[idx] = __float2half_rn(kv[idx]);
        }
        return;
    }
    b -= KV_BLKS;
    {
        int t = b * 128 + tid;
        if (t < NHEADS * NWIN * NWIN) {
            int h = t / (NWIN * NWIN), ij = t % (NWIN * NWIN);
            int i = ij / NWIN, j = ij - i * NWIN;
            bmh[h * 2500 + i * 50 + j] = __float2half_rn(btab[rel[ij] * NHEADS + h]);
        }
    }
}

// ============================================================
// LayerNorm (fp16 rows) -> fp16, vectorized half2, 192 thr/row
// ============================================================
__global__ void __launch_bounds__(192)
ln_kernel_h(const fp16* __restrict__ xin, const float* __restrict__ g,
            const float* __restrict__ bb, fp16* __restrict__ oh)
{
    int r = blockIdx.x;
    const __half2* xr2 = (const __half2*)(xin + (size_t)r * CDIM);
    int tid = threadIdx.x;                 // 0..191, each owns cols 2t, 2t+1
    __half2 hv = xr2[tid];
    float v0 = __low2float(hv), v1 = __high2float(hv);
    float s = v0 + v1, ss = v0 * v0 + v1 * v1;
    #pragma unroll
    for (int o = 16; o; o >>= 1) {
        s  += __shfl_xor_sync(0xffffffffu, s,  o);
        ss += __shfl_xor_sync(0xffffffffu, ss, o);
    }
    __shared__ float rs[6], rss[6], smean, sinv;
    int warp = tid >> 5, lane = tid & 31;
    if (lane == 0) { rs[warp] = s; rss[warp] = ss; }
    __syncthreads();
    if (tid == 0) {
        float S = 0.f, SS = 0.f;
        #pragma unroll
        for (int i = 0; i < 6; ++i) { S += rs[i]; SS += rss[i]; }
        float m = S * (1.0f / 384.0f);
        smean = m;
        sinv = rsqrtf(SS * (1.0f / 384.0f) - m * m + 1e-5f);
    }
    __syncthreads();
    int c0 = tid * 2;
    float y0 = (v0 - smean) * sinv * g[c0]     + bb[c0];
    float y1 = (v1 - smean) * sinv * g[c0 + 1] + bb[c0 + 1];
    ((__half2*)(oh + (size_t)r * CDIM))[tid] = __floats2half2_rn(y0, y1);
}

// ============================================================
// fp16 tensor-core GEMM: 128x128, KC=64, 3-stage cp.async.
// ============================================================
enum { EPI_Q = 0, EPI_PROJ = 1, EPI_GELU = 2, EPI_FC2 = 3 };
#define TILE_B   18432
#define STAGE_B  36864
#define NSTAGE   3
#define SMEM_DYN (NSTAGE * STAGE_B)   // 110592

template <int EPI>
__global__ void __launch_bounds__(256, 2)
mma_gemm(const fp16* __restrict__ Am, const fp16* __restrict__ Bm,
         int K, const float* __restrict__ bias,
         float* __restrict__ Cf, fp16* __restrict__ Ch,
         const float* __restrict__ resid, const fp16* __restrict__ residh,
         float scale)
{
    extern __shared__ char sm_raw[];
    unsigned sbase = smem_u32(sm_raw);

    int tid = threadIdx.x, wid = tid >> 5, lane = tid & 31;
    int bm = blockIdx.y * 128, bn = blockIdx.x * 128;
    int m0 = (wid & 3) * 32, n0 = (wid >> 2) * 64;

    int rowL[8], chL[8], tileL[8];
    #pragma unroll
    for (int t = 0; t < 8; ++t) {
        int item = tid + t * 256;
        tileL[t] = item >> 10;
        int rem = item & 1023;
        rowL[t] = rem >> 3; chL[t] = rem & 7;
    }

    auto load_stage = [&](int stage, int k0) {
        unsigned db = sbase + stage * STAGE_B;
        #pragma unroll
        for (int t = 0; t < 8; ++t) {
            const fp16* src = (tileL[t] ? Bm : Am)
                + (size_t)((tileL[t] ? bn : bm) + rowL[t]) * K + k0 + chL[t] * 8;
            cp16(db + tileL[t] * TILE_B + rowL[t] * 144 + chL[t] * 16, src);
        }
        CP_COMMIT();
    };

    float acc[2][8][4];
    #pragma unroll
    for (int a = 0; a < 2; ++a)
        #pragma unroll
        for (int b = 0; b < 8; ++b)
            #pragma unroll
            for (int c = 0; c < 4; ++c) acc[a][b][c] = 0.0f;

    int niter = K >> 6;
    load_stage(0, 0);
    load_stage(1, 64);

    unsigned a_base[2], b_base[4];
    #pragma unroll
    for (int mt = 0; mt < 2; ++mt)
        a_base[mt] = (m0 + mt * 16 + (lane & 15)) * 144 + (lane >> 4) * 16;
    #pragma unroll
    for (int nt = 0; nt < 4; ++nt)
        b_base[nt] = TILE_B + (n0 + nt * 16 + (lane & 15)) * 144 + (lane >> 4) * 16;

    int st = 0;
    for (int it = 0; it < niter; ++it) {
        CP_WAIT(1);
        __syncthreads();

        if (it + 2 < niter) {
            int pst = st + 2; if (pst >= 3) pst -= 3;
            load_stage(pst, (it + 2) * 64);
        } else CP_COMMIT();

        unsigned base = sbase + st * STAGE_B;

        #pragma unroll
        for (int kp = 0; kp < 2; ++kp) {
            unsigned koff = kp * 64;
            unsigned ah[2][2][4], bh[2][4][4];
            #pragma unroll
            for (int ks = 0; ks < 2; ++ks)
                #pragma unroll
                for (int mt = 0; mt < 2; ++mt)
                    LDSM4(ah[ks][mt], base + a_base[mt] + koff + ks * 32);
            #pragma unroll
            for (int ks = 0; ks < 2; ++ks)
                #pragma unroll
                for (int nt = 0; nt < 4; ++nt)
                    LDSM4(bh[ks][nt], base + b_base[nt] + koff + ks * 32);

            #pragma unroll
            for (int ks = 0; ks < 2; ++ks)
                #pragma unroll
                for (int nt = 0; nt < 4; ++nt)
                    #pragma unroll
                    for (int mt = 0; mt < 2; ++mt) {
                        MMA_F16(acc[mt][nt * 2 + 0], ah[ks][mt], bh[ks][nt][0], bh[ks][nt][2]);
                        MMA_F16(acc[mt][nt * 2 + 1], ah[ks][mt], bh[ks][nt][1], bh[ks][nt][3]);
                    }
        }
        if (++st >= 3) st = 0;
    }

    int r_in = lane >> 2, c_in = (lane & 3) * 2;
    #pragma unroll
    for (int mt = 0; mt < 2; ++mt) {
        #pragma unroll
        for (int j = 0; j < 8; ++j) {
            int col = bn + n0 + j * 8 + c_in;
            #pragma unroll
            for (int hf = 0; hf < 2; ++hf) {
                int row = bm + m0 + mt * 16 + r_in + hf * 8;
                float v0 = acc[mt][j][hf * 2 + 0];
                float v1 = acc[mt][j][hf * 2 + 1];
                if (EPI == EPI_Q) {
                    int w = row / NWIN, n = row % NWIN;
                    int hd = col >> 5, d = col & 31;
                    __half2 hp;
                    hp.x = __float2half_rn((v0 + bias[col]) * scale);
                    hp.y = __float2half_rn((v1 + bias[col + 1]) * scale);
                    *(__half2*)&Ch[((size_t)(w * NHEADS + hd) * NWIN + n) * HDIM + d] = hp;
                } else if (EPI == EPI_PROJ) {
                    int w = row / NWIN, n = row % NWIN;
                    int bimg = w >> 6, wy = (w >> 3) & 7, wx = w & 7;
                    int iy = n / 7, ix = n % 7;
                    size_t o = ((size_t)bimg * 3136 + (wy * 7 + iy) * 56 + (wx * 7 + ix)) * CDIM + col;
                    float2 r2 = *(const float2*)&resid[o];
                    __half2 hp;
                    hp.x = __float2half_rn(v0 + bias[col] + r2.x);
                    hp.y = __float2half_rn(v1 + bias[col + 1] + r2.y);
                    *(__half2*)&Ch[o] = hp;
                } else if (EPI == EPI_GELU) {
                    float a0 = v0 + bias[col], a1 = v1 + bias[col + 1];
                    float g0 = 0.5f * a0 * (1.0f + erff(a0 * 0.70710678118654752f));
                    float g1 = 0.5f * a1 * (1.0f + erff(a1 * 0.70710678118654752f));
                    __half2 hp;
                    hp.x = __float2half_rn(g0); hp.y = __float2half_rn(g1);
                    *(__half2*)&Ch[(size_t)row * HIDDEN + col] = hp;
                } else {
                    size_t o = (size_t)row * CDIM + col;
                    __half2 rh = *(const __half2*)&residh[o];
                    *(float2*)&Cf[o] = make_float2(v0 + bias[col] + __low2float(rh),
                                                   v1 + bias[col + 1] + __high2float(rh));
                }
            }
        }
    }
}

// ============================================================
// Tensor-core windowed attention (R12 per-window version:
// register softmax, one __syncthreads, V row-major + trans ldmatrix)
// ============================================================
#define QK_PITCH 40

__global__ void __launch_bounds__(128)
attn_tc(const fp16* __restrict__ q, const fp16* __restrict__ kvh,
        const fp16* __restrict__ bmh, fp16* __restrict__ ao)
{
    __shared__ fp16 sq[64 * QK_PITCH];
    __shared__ fp16 sk[64 * QK_PITCH];
    __shared__ fp16 sv[64 * QK_PITCH];

    int blk = blockIdx.x;
    int w = blk / NHEADS, h = blk - w * NHEADS;
    int bimg = w >> 6;
    int tid = threadIdx.x, wid = tid >> 5, lane = tid & 31;

    const fp16* qp = q + (size_t)blk * (NWIN * HDIM);
    const fp16* kp = kvh + (size_t)(bimg * NHEADS + h) * (NWIN * HDIM);
    const fp16* vp = kp + (size_t)16 * NHEADS * NWIN * HDIM;

    for (int t = tid; t < 196; t += 128) {
        int row = t >> 2, col = (t & 3) * 8;
        *(uint4*)&sq[row * QK_PITCH + col] = ((const uint4*)qp)[t];
        *(uint4*)&sk[row * QK_PITCH + col] = ((const uint4*)kp)[t];
        *(uint4*)&sv[row * QK_PITCH + col] = ((const uint4*)vp)[t];
    }
    for (int t = tid; t < 60; t += 128) {
        int row = 49 + (t >> 2), col = (t & 3) * 8;
        *(uint4*)&sv[row * QK_PITCH + col] = make_uint4(0, 0, 0, 0);
    }
    __syncthreads();

    unsigned sq_u = smem_u32(sq), sk_u = smem_u32(sk), sv_u = smem_u32(sv);
    int m0 = wid * 16;

    float acc[8][4];
    #pragma unroll
    for (int a = 0; a < 8; ++a)
        #pragma unroll
        for (int c = 0; c < 4; ++c) acc[a][c] = 0.0f;
    {
        unsigned ah[2][4], bh[2][4][4];
        #pragma unroll
        for (int kt = 0; kt < 2; ++kt)
            LDSM4(ah[kt], sq_u + ((m0 + (lane & 15)) * QK_PITCH + kt * 16 + (lane >> 4) * 8) * 2);
        #pragma unroll
        for (int kt = 0; kt < 2; ++kt)
            #pragma unroll
            for (int nt = 0; nt < 4; ++nt)
                LDSM4(bh[kt][nt], sk_u + ((nt * 16 + (lane & 15)) * QK_PITCH + kt * 16 + (lane >> 4) * 8) * 2);
        #pragma unroll
        for (int kt = 0; kt < 2; ++kt)
            #pragma unroll
            for (int nt = 0; nt < 4; ++nt) {
                MMA_F16(acc[nt * 2 + 0], ah[kt], bh[kt][nt][0], bh[kt][nt][2]);
                MMA_F16(acc[nt * 2 + 1], ah[kt], bh[kt][nt][1], bh[kt][nt][3]);
            }
    }

    int r = lane >> 2, c2 = (lane & 3) * 2;
    int i1 = m0 + r, i2 = i1 + 8;
    const fp16* bp = bmh + h * 2500;
    float v1[16], v2[16];
    #pragma unroll
    for (int nj = 0; nj < 8; ++nj) {
        int j0 = nj * 8 + c2;
        float b0 = 0.f, b1 = 0.f, b2 = 0.f, b3 = 0.f;
        if (j0 < 49) {
            if (i1 < 49) {
                __half2 bb = *(const __half2*)&bp[i1 * 50 + j0];
                b0 = __low2float(bb); b1 = __high2float(bb);
            }
            if (i2 < 49) {
                __half2 bb = *(const __half2*)&bp[i2 * 50 + j0];
                b2 = __low2float(bb); b3 = __high2float(bb);
            }
        }
        v1[nj * 2 + 0] = (j0     < 49) ? acc[nj][0] + b0 : -1e30f;
        v1[nj * 2 + 1] = (j0 + 1 < 49) ? acc[nj][1] + b1 : -1e30f;
        v2[nj * 2 + 0] = (j0     < 49) ? acc[nj][2] + b2 : -1e30f;
        v2[nj * 2 + 1] = (j0 + 1 < 49) ? acc[nj][3] + b3 : -1e30f;
    }
    float m1 = -1e30f, m2 = -1e30f;
    #pragma unroll
    for (int t = 0; t < 16; ++t) { m1 = fmaxf(m1, v1[t]); m2 = fmaxf(m2, v2[t]); }
    m1 = fmaxf(m1, __shfl_xor_sync(0xffffffffu, m1, 1));
    m1 = fmaxf(m1, __shfl_xor_sync(0xffffffffu, m1, 2));
    m2 = fmaxf(m2, __shfl_xor_sync(0xffffffffu, m2, 1));
    m2 = fmaxf(m2, __shfl_xor_sync(0xffffffffu, m2, 2));
    float s1 = 0.f, s2 = 0.f;
    #pragma unroll
    for (int t = 0; t < 16; ++t) {
        v1[t] = __expf(v1[t] - m1); s1 += v1[t];
        v2[t] = __expf(v2[t] - m2); s2 += v2[t];
    }
    s1 += __shfl_xor_sync(0xffffffffu, s1, 1);
    s1 += __shfl_xor_sync(0xffffffffu, s1, 2);
    s2 += __shfl_xor_sync(0xffffffffu, s2, 1);
    s2 += __shfl_xor_sync(0xffffffffu, s2, 2);
    float inv1 = 1.0f / s1, inv2 = 1.0f / s2;

    unsigned pa[4][4];
    #pragma unroll
    for (int kt = 0; kt < 4; ++kt) {
        __half2 t0 = __floats2half2_rn(v1[4 * kt + 0] * inv1, v1[4 * kt + 1] * inv1);
        __half2 t1 = __floats2half2_rn(v2[4 * kt + 0] * inv2, v2[4 * kt + 1] * inv2);
        __half2 t2 = __floats2half2_rn(v1[4 * kt + 2] * inv1, v1[4 * kt + 3] * inv1);
        __half2 t3 = __floats2half2_rn(v2[4 * kt + 2] * inv2, v2[4 * kt + 3] * inv2);
        pa[kt][0] = *(unsigned*)&t0;
        pa[kt][1] = *(unsigned*)&t1;
        pa[kt][2] = *(unsigned*)&t2;
        pa[kt][3] = *(unsigned*)&t3;
    }

    float oa[4][4];
    #pragma unroll
    for (int a = 0; a < 4; ++a)
        #pragma unroll
        for (int c = 0; c < 4; ++c) oa[a][c] = 0.0f;
    #pragma unroll
    for (int kt = 0; kt < 4; ++kt) {
        #pragma unroll
        for (int nt = 0; nt < 2; ++nt) {
            unsigned bh2[4];
            LDSM4T(bh2, sv_u + ((kt * 16 + (lane & 15)) * QK_PITCH + nt * 16 + (lane >> 4) * 8) * 2);
            MMA_F16(oa[nt * 2 + 0], pa[kt], bh2[0], bh2[1]);
            MMA_F16(oa[nt * 2 + 1], pa[kt], bh2[2], bh2[3]);
        }
    }
    #pragma unroll
    for (int nt = 0; nt < 4; ++nt) {
        int d = nt * 8 + c2;
        if (i1 < NWIN) {
            __half2 hp;
            hp.x = __float2half_rn(oa[nt][0]); hp.y = __float2half_rn(oa[nt][1]);
            *(__half2*)&ao[((size_t)w * NWIN + i1) * CDIM + h * HDIM + d] = hp;
        }
        if (i2 < NWIN) {
            __half2 hp;
            hp.x = __float2half_rn(oa[nt][2]); hp.y = __float2half_rn(oa[nt][3]);
            *(__half2*)&ao[((size_t)w * NWIN + i2) * CDIM + h * HDIM + d] = hp;
        }
    }
}

// ============================================================
// launch
// ============================================================
extern "C" void kernel_launch(void* const* d_in, const int* in_sizes, int n_in,
                              void* d_out, int out_size)
{
    (void)in_sizes; (void)n_in; (void)out_size;
    const float* x     = (const float*)d_in[0];
    const float* kv    = (const float*)d_in[1];
    const int*   rel   = (const int*)d_in[2];
    const float* g1    = (const float*)d_in[5];
    const float* b1    = (const float*)d_in[6];
    const float* Wqkv  = (const float*)d_in[7];
    const float* bqkv  = (const float*)d_in[8];
    const float* btab  = (const float*)d_in[9];
    const float* Wproj = (const float*)d_in[10];
    const float* bproj = (const float*)d_in[11];
    const float* g2    = (const float*)d_in[12];
    const float* b2    = (const float*)d_in[13];
    const float* Wfc1  = (const float*)d_in[14];
    const float* bfc1  = (const float*)d_in[15];
    const float* Wfc2  = (const float*)d_in[16];
    const float* bfc2  = (const float*)d_in[17];
    float* out = (float*)d_out;

    static fp16 *x1h = nullptr;
    static fp16 *hw, *qh, *ao, *h2, *mid, *wq, *wp, *w1, *w2, *kvh, *bmh;
    if (!x1h) {
        cudaGetSymbolAddress((void**)&x1h, g_x1h);
        cudaGetSymbolAddress((void**)&bmh, g_bmh);
        cudaGetSymbolAddress((void**)&hw,  g_hw);
        cudaGetSymbolAddress((void**)&qh,  g_qh);
        cudaGetSymbolAddress((void**)&ao,  g_ao);
        cudaGetSymbolAddress((void**)&h2,  g_h2);
        cudaGetSymbolAddress((void**)&mid, g_mid);
        cudaGetSymbolAddress((void**)&wq,  g_wq);
        cudaGetSymbolAddress((void**)&wp,  g_wp);
        cudaGetSymbolAddress((void**)&w1,  g_w1);
        cudaGetSymbolAddress((void**)&w2,  g_w2);
        cudaGetSymbolAddress((void**)&kvh, g_kvh);
        cudaFuncSetAttribute(mma_gemm<EPI_Q>,    cudaFuncAttributeMaxDynamicSharedMemorySize, SMEM_DYN);
        cudaFuncSetAttribute(mma_gemm<EPI_PROJ>, cudaFuncAttributeMaxDynamicSharedMemorySize, SMEM_DYN);
        cudaFuncSetAttribute(mma_gemm<EPI_GELU>, cudaFuncAttributeMaxDynamicSharedMemorySize, SMEM_DYN);
        cudaFuncSetAttribute(mma_gemm<EPI_FC2>,  cudaFuncAttributeMaxDynamicSharedMemorySize, SMEM_DYN);
    }

    const float qscale = 0.17677669529663687f;

    pre_kernel<<<PRE_GRID, 128>>>(x, g1, b1, hw,
                                  Wqkv, Wproj, Wfc1, Wfc2, kv, rel, btab,
                                  wq, wp, w1, w2, kvh, bmh);

    mma_gemm<EPI_Q><<<dim3(3, 392), 256, SMEM_DYN>>>(hw, wq, 384,
        bqkv, nullptr, qh, nullptr, nullptr, qscale);

    attn_tc<<<BWIN * NHEADS, 128>>>(qh, kvh, bmh, ao);

    mma_gemm<EPI_PROJ><<<dim3(3, 392), 256, SMEM_DYN>>>(ao, wp, 384,
        bproj, nullptr, x1h, x, nullptr, 0.0f);

    ln_kernel_h<<<MROWS, 192>>>(x1h, g2, b2, h2);

    mma_gemm<EPI_GELU><<<dim3(12, 392), 256, SMEM_DYN>>>(h2, w1, 384,
        bfc1, nullptr, mid, nullptr, nullptr, 0.0f);

    mma_gemm<EPI_FC2><<<dim3(3, 392), 256, SMEM_DYN>>>(mid, w2, 1536,
        bfc2, out, nullptr, nullptr, x1h, 0.0f);
}

// round 15
// speedup vs baseline: 1.3004x; 1.0114x over previous
#include <cuda_runtime.h>
#include <cuda_fp16.h>
#include <math.h>

// Problem constants
#define MROWS  50176
#define CDIM   384
#define HIDDEN 1536
#define NHEADS 12
#define HDIM   32
#define NWIN   49
#define BWIN   1024
#define KV_ELEMS (2 * 16 * NHEADS * NWIN * HDIM)   // 602112

typedef __half fp16;

// -------- scratch (device globals; no allocations allowed) --------
__device__ fp16 g_x1h[(size_t)MROWS * CDIM];
__device__ fp16 g_hw [(size_t)MROWS * CDIM];
__device__ fp16 g_qh [(size_t)MROWS * CDIM];
__device__ fp16 g_ao [(size_t)MROWS * CDIM];
__device__ fp16 g_h2 [(size_t)MROWS * CDIM];
__device__ fp16 g_mid[(size_t)MROWS * HIDDEN];
__device__ fp16 g_wq [384 * 384];
__device__ fp16 g_wp [384 * 384];
__device__ fp16 g_w1 [384 * 1536];
__device__ fp16 g_w2 [1536 * 384];
__device__ fp16 g_kvh[KV_ELEMS];
__device__ fp16 g_bmh[NHEADS * 50 * 50];   // fp16 bias matrix, pitch 50

// ================= PTX helpers =================
__device__ __forceinline__ unsigned smem_u32(const void* p) {
    unsigned a;
    asm("{ .reg .u64 t; cvta.to.shared.u64 t, %1; cvt.u32.u64 %0, t; }" : "=r"(a) : "l"(p));
    return a;
}
__device__ __forceinline__ void cp16(unsigned dst, const void* src) {
    asm volatile("cp.async.cg.shared.global [%0], [%1], 16;" :: "r"(dst), "l"(src) : "memory");
}
#define CP_COMMIT() asm volatile("cp.async.commit_group;" ::: "memory")
#define CP_WAIT(n)  asm volatile("cp.async.wait_group %0;" :: "n"(n) : "memory")

#define LDSM4(r, a)                                                                \
    asm volatile("ldmatrix.sync.aligned.m8n8.x4.shared.b16 {%0,%1,%2,%3}, [%4];"   \
        : "=r"((r)[0]), "=r"((r)[1]), "=r"((r)[2]), "=r"((r)[3]) : "r"(a))

#define LDSM4T(r, a)                                                               \
    asm volatile("ldmatrix.sync.aligned.m8n8.x4.trans.shared.b16 {%0,%1,%2,%3}, [%4];" \
        : "=r"((r)[0]), "=r"((r)[1]), "=r"((r)[2]), "=r"((r)[3]) : "r"(a))

#define MMA_F16(d, a, b0, b1)                                                      \
    asm volatile("mma.sync.aligned.m16n8k16.row.col.f32.f16.f16.f32 "              \
        "{%0,%1,%2,%3}, {%4,%5,%6,%7}, {%8,%9}, {%0,%1,%2,%3};"                    \
        : "+f"((d)[0]), "+f"((d)[1]), "+f"((d)[2]), "+f"((d)[3])                    \
        : "r"((a)[0]), "r"((a)[1]), "r"((a)[2]), "r"((a)[3]), "r"(b0), "r"(b1))

// ============================================================
// pre_kernel: LN1 (+window partition) fused with ALL conversions.
// ============================================================
#define WT_TILES 1440
#define KV_BLKS  588
#define BM_BLKS  226
#define PRE_GRID (MROWS + WT_TILES + KV_BLKS + BM_BLKS)

__global__ void pre_kernel(const float* __restrict__ x, const float* __restrict__ g,
                           const float* __restrict__ bb, fp16* __restrict__ oh,
                           const float* __restrict__ Wq, const float* __restrict__ Wp,
                           const float* __restrict__ W1, const float* __restrict__ W2,
                           const float* __restrict__ kv,
                           const int* __restrict__ rel, const float* __restrict__ btab,
                           fp16* __restrict__ oq, fp16* __restrict__ op,
                           fp16* __restrict__ o1, fp16* __restrict__ o2,
                           fp16* __restrict__ okv, fp16* __restrict__ bmh)
{
    __shared__ float tile[32][33];
    __shared__ float rs[4], rss[4], smean, sinv;

    int b = blockIdx.x;
    int tid = threadIdx.x;

    if (b < MROWS) {
        int w = b / NWIN, n = b % NWIN;
        int bimg = w >> 6, wy = (w >> 3) & 7, wx = w & 7;
        int iy = n / 7, ix = n % 7;
        size_t srow = (size_t)bimg * 3136 + (wy * 7 + iy) * 56 + (wx * 7 + ix);
        const float* xr = x + srow * CDIM;
        float v0 = xr[tid], v1 = xr[tid + 128], v2 = xr[tid + 256];
        float s = v0 + v1 + v2, ss = v0 * v0 + v1 * v1 + v2 * v2;
        #pragma unroll
        for (int o = 16; o; o >>= 1) {
            s  += __shfl_xor_sync(0xffffffffu, s,  o);
            ss += __shfl_xor_sync(0xffffffffu, ss, o);
        }
        int warp = tid >> 5, lane = tid & 31;
        if (lane == 0) { rs[warp] = s; rss[warp] = ss; }
        __syncthreads();
        if (tid == 0) {
            float S = rs[0] + rs[1] + rs[2] + rs[3];
            float SS = rss[0] + rss[1] + rss[2] + rss[3];
            float m = S * (1.0f / 384.0f);
            smean = m;
            sinv = rsqrtf(SS * (1.0f / 384.0f) - m * m + 1e-5f);
        }
        __syncthreads();
        size_t orow = (size_t)b * CDIM;
        #pragma unroll
        for (int c = 0; c < 3; ++c) {
            float vv = (c == 0 ? v0 : c == 1 ? v1 : v2);
            int col = tid + c * 128;
            oh[orow + col] = __float2half_rn((vv - smean) * sinv * g[col] + bb[col]);
        }
        return;
    }
    b -= MROWS;
    if (b < WT_TILES) {
        const float* W; fp16* o; int Kd, ld, tiles_n, tt;
        if (b < 144)      { W = Wq; o = oq; Kd = 384;  ld = 1152; tiles_n = 12; tt = b; }
        else if (b < 288) { W = Wp; o = op; Kd = 384;  ld = 384;  tiles_n = 12; tt = b - 144; }
        else if (b < 864) { W = W1; o = o1; Kd = 384;  ld = 1536; tiles_n = 48; tt = b - 288; }
        else              { W = W2; o = o2; Kd = 1536; ld = 384;  tiles_n = 12; tt = b - 864; }
        int tk = tt / tiles_n, tn = tt % tiles_n;
        int k0 = tk * 32, n0 = tn * 32;
        int tx = tid & 31, ty = tid >> 5;
        #pragma unroll
        for (int i = 0; i < 8; ++i)
            tile[ty + 4 * i][tx] = W[(size_t)(k0 + ty + 4 * i) * ld + n0 + tx];
        __syncthreads();
        #pragma unroll
        for (int i = 0; i < 8; ++i)
            o[(size_t)(n0 + ty + 4 * i) * Kd + k0 + tx] = __float2half_rn(tile[tx][ty + 4 * i]);
        return;
    }
    b -= WT_TILES;
    if (b < KV_BLKS) {
        int base = b * 1024 + tid;
        #pragma unroll
        for (int i = 0; i < 8; ++i) {
            int idx = base + i * 128;
            if (idx < KV_ELEMS) okv[idx] = __float2half_rn(kv[idx]);
        }
        return;
    }
    b -= KV_BLKS;
    {
        int t = b * 128 + tid;
        if (t < NHEADS * NWIN * NWIN) {
            int h = t / (NWIN * NWIN), ij = t % (NWIN * NWIN);
            int i = ij / NWIN, j = ij - i * NWIN;
            bmh[h * 2500 + i * 50 + j] = __float2half_rn(btab[rel[ij] * NHEADS + h]);
        }
    }
}

// ============================================================
// LayerNorm (fp16 input rows) -> fp16  (R12 proven version)
// ============================================================
__global__ void ln_kernel_h(const fp16* __restrict__ xin, const float* __restrict__ g,
                            const float* __restrict__ bb, fp16* __restrict__ oh)
{
    int r = blockIdx.x;
    const fp16* xr = xin + (size_t)r * CDIM;
    int tid = threadIdx.x;
    float v0 = __half2float(xr[tid]);
    float v1 = __half2float(xr[tid + 128]);
    float v2 = __half2float(xr[tid + 256]);
    float s = v0 + v1 + v2, ss = v0 * v0 + v1 * v1 + v2 * v2;
    #pragma unroll
    for (int o = 16; o; o >>= 1) {
        s  += __shfl_xor_sync(0xffffffffu, s,  o);
        ss += __shfl_xor_sync(0xffffffffu, ss, o);
    }
    __shared__ float rs[4], rss[4], smean, sinv;
    int warp = tid >> 5, lane = tid & 31;
    if (lane == 0) { rs[warp] = s; rss[warp] = ss; }
    __syncthreads();
    if (tid == 0) {
        float S = rs[0] + rs[1] + rs[2] + rs[3];
        float SS = rss[0] + rss[1] + rss[2] + rss[3];
        float m = S * (1.0f / 384.0f);
        smean = m;
        sinv = rsqrtf(SS * (1.0f / 384.0f) - m * m + 1e-5f);
    }
    __syncthreads();
    size_t orow = (size_t)r * CDIM;
    #pragma unroll
    for (int c = 0; c < 3; ++c) {
        float vv = (c == 0 ? v0 : c == 1 ? v1 : v2);
        int col = tid + c * 128;
        oh[orow + col] = __float2half_rn((vv - smean) * sinv * g[col] + bb[col]);
    }
}

// ============================================================
// fp16 tensor-core GEMM: 128x128, KC=64, 3-stage cp.async.
// ============================================================
enum { EPI_Q = 0, EPI_PROJ = 1, EPI_GELU = 2, EPI_FC2 = 3 };
#define TILE_B   18432
#define STAGE_B  36864
#define NSTAGE   3
#define SMEM_DYN (NSTAGE * STAGE_B)   // 110592

template <int EPI>
__global__ void __launch_bounds__(256, 2)
mma_gemm(const fp16* __restrict__ Am, const fp16* __restrict__ Bm,
         int K, const float* __restrict__ bias,
         float* __restrict__ Cf, fp16* __restrict__ Ch,
         const float* __restrict__ resid, const fp16* __restrict__ residh,
         float scale)
{
    extern __shared__ char sm_raw[];
    unsigned sbase = smem_u32(sm_raw);

    int tid = threadIdx.x, wid = tid >> 5, lane = tid & 31;
    int bm = blockIdx.y * 128, bn = blockIdx.x * 128;
    int m0 = (wid & 3) * 32, n0 = (wid >> 2) * 64;

    int rowL[8], chL[8], tileL[8];
    #pragma unroll
    for (int t = 0; t < 8; ++t) {
        int item = tid + t * 256;
        tileL[t] = item >> 10;
        int rem = item & 1023;
        rowL[t] = rem >> 3; chL[t] = rem & 7;
    }

    auto load_stage = [&](int stage, int k0) {
        unsigned db = sbase + stage * STAGE_B;
        #pragma unroll
        for (int t = 0; t < 8; ++t) {
            const fp16* src = (tileL[t] ? Bm : Am)
                + (size_t)((tileL[t] ? bn : bm) + rowL[t]) * K + k0 + chL[t] * 8;
            cp16(db + tileL[t] * TILE_B + rowL[t] * 144 + chL[t] * 16, src);
        }
        CP_COMMIT();
    };

    float acc[2][8][4];
    #pragma unroll
    for (int a = 0; a < 2; ++a)
        #pragma unroll
        for (int b = 0; b < 8; ++b)
            #pragma unroll
            for (int c = 0; c < 4; ++c) acc[a][b][c] = 0.0f;

    int niter = K >> 6;
    load_stage(0, 0);
    load_stage(1, 64);

    unsigned a_base[2], b_base[4];
    #pragma unroll
    for (int mt = 0; mt < 2; ++mt)
        a_base[mt] = (m0 + mt * 16 + (lane & 15)) * 144 + (lane >> 4) * 16;
    #pragma unroll
    for (int nt = 0; nt < 4; ++nt)
        b_base[nt] = TILE_B + (n0 + nt * 16 + (lane & 15)) * 144 + (lane >> 4) * 16;

    int st = 0;
    for (int it = 0; it < niter; ++it) {
        CP_WAIT(1);
        __syncthreads();

        if (it + 2 < niter) {
            int pst = st + 2; if (pst >= 3) pst -= 3;
            load_stage(pst, (it + 2) * 64);
        } else CP_COMMIT();

        unsigned base = sbase + st * STAGE_B;

        #pragma unroll
        for (int kp = 0; kp < 2; ++kp) {
            unsigned koff = kp * 64;
            unsigned ah[2][2][4], bh[2][4][4];
            #pragma unroll
            for (int ks = 0; ks < 2; ++ks)
                #pragma unroll
                for (int mt = 0; mt < 2; ++mt)
                    LDSM4(ah[ks][mt], base + a_base[mt] + koff + ks * 32);
            #pragma unroll
            for (int ks = 0; ks < 2; ++ks)
                #pragma unroll
                for (int nt = 0; nt < 4; ++nt)
                    LDSM4(bh[ks][nt], base + b_base[nt] + koff + ks * 32);

            #pragma unroll
            for (int ks = 0; ks < 2; ++ks)
                #pragma unroll
                for (int nt = 0; nt < 4; ++nt)
                    #pragma unroll
                    for (int mt = 0; mt < 2; ++mt) {
                        MMA_F16(acc[mt][nt * 2 + 0], ah[ks][mt], bh[ks][nt][0], bh[ks][nt][2]);
                        MMA_F16(acc[mt][nt * 2 + 1], ah[ks][mt], bh[ks][nt][1], bh[ks][nt][3]);
                    }
        }
        if (++st >= 3) st = 0;
    }

    int r_in = lane >> 2, c_in = (lane & 3) * 2;
    #pragma unroll
    for (int mt = 0; mt < 2; ++mt) {
        #pragma unroll
        for (int j = 0; j < 8; ++j) {
            int col = bn + n0 + j * 8 + c_in;
            #pragma unroll
            for (int hf = 0; hf < 2; ++hf) {
                int row = bm + m0 + mt * 16 + r_in + hf * 8;
                float v0 = acc[mt][j][hf * 2 + 0];
                float v1 = acc[mt][j][hf * 2 + 1];
                if (EPI == EPI_Q) {
                    int w = row / NWIN, n = row % NWIN;
                    int hd = col >> 5, d = col & 31;
                    __half2 hp;
                    hp.x = __float2half_rn((v0 + bias[col]) * scale);
                    hp.y = __float2half_rn((v1 + bias[col + 1]) * scale);
                    *(__half2*)&Ch[((size_t)(w * NHEADS + hd) * NWIN + n) * HDIM + d] = hp;
                } else if (EPI == EPI_PROJ) {
                    int w = row / NWIN, n = row % NWIN;
                    int bimg = w >> 6, wy = (w >> 3) & 7, wx = w & 7;
                    int iy = n / 7, ix = n % 7;
                    size_t o = ((size_t)bimg * 3136 + (wy * 7 + iy) * 56 + (wx * 7 + ix)) * CDIM + col;
                    float2 r2 = *(const float2*)&resid[o];
                    __half2 hp;
                    hp.x = __float2half_rn(v0 + bias[col] + r2.x);
                    hp.y = __float2half_rn(v1 + bias[col + 1] + r2.y);
                    *(__half2*)&Ch[o] = hp;
                } else if (EPI == EPI_GELU) {
                    float a0 = v0 + bias[col], a1 = v1 + bias[col + 1];
                    float g0 = 0.5f * a0 * (1.0f + erff(a0 * 0.70710678118654752f));
                    float g1 = 0.5f * a1 * (1.0f + erff(a1 * 0.70710678118654752f));
                    __half2 hp;
                    hp.x = __float2half_rn(g0); hp.y = __float2half_rn(g1);
                    *(__half2*)&Ch[(size_t)row * HIDDEN + col] = hp;
                } else {
                    size_t o = (size_t)row * CDIM + col;
                    __half2 rh = *(const __half2*)&residh[o];
                    *(float2*)&Cf[o] = make_float2(v0 + bias[col] + __low2float(rh),
                                                   v1 + bias[col + 1] + __high2float(rh));
                }
            }
        }
    }
}

// ============================================================
// Tensor-core windowed attention: TWO windows per 256-thread
// block, processed by disjoint warp quads IN PARALLEL (no
// serialization). k/v/bias shared across the pair. One barrier.
// ============================================================
#define QK_PITCH 40

__global__ void __launch_bounds__(256)
attn_tc(const fp16* __restrict__ q, const fp16* __restrict__ kvh,
        const fp16* __restrict__ bmh, fp16* __restrict__ ao)
{
    __shared__ fp16 sq[2][64 * QK_PITCH];
    __shared__ fp16 sk[64 * QK_PITCH];
    __shared__ fp16 sv[64 * QK_PITCH];

    int blk = blockIdx.x;                 // pair*12 + h, pair in [0,512)
    int pair = blk / NHEADS, h = blk - pair * NHEADS;
    int w0 = pair * 2;
    int bimg = w0 >> 6;
    int tid = threadIdx.x, wid = tid >> 5, lane = tid & 31;
    int win = wid >> 2;                   // 0 or 1: which window this warp handles
    int m0 = (wid & 3) * 16;

    const fp16* kp = kvh + (size_t)(bimg * NHEADS + h) * (NWIN * HDIM);
    const fp16* vp = kp + (size_t)16 * NHEADS * NWIN * HDIM;
    const fp16* qp0 = q + (size_t)(w0 * NHEADS + h) * (NWIN * HDIM);
    const fp16* qp1 = qp0 + (size_t)NHEADS * (NWIN * HDIM);

    // q (both windows): 392 uint4; k, v: 196 each
    for (int t = tid; t < 392; t += 256) {
        int wx = t >= 196;
        int tt = wx ? t - 196 : t;
        int row = tt >> 2, col = (tt & 3) * 8;
        *(uint4*)&sq[wx][row * QK_PITCH + col] = ((const uint4*)(wx ? qp1 : qp0))[tt];
    }
    for (int t = tid; t < 196; t += 256) {
        int row = t >> 2, col = (t & 3) * 8;
        *(uint4*)&sk[row * QK_PITCH + col] = ((const uint4*)kp)[t];
        *(uint4*)&sv[row * QK_PITCH + col] = ((const uint4*)vp)[t];
    }
    for (int t = tid; t < 60; t += 256) {   // zero-pad V k-rows 49..63
        int row = 49 + (t >> 2), col = (t & 3) * 8;
        *(uint4*)&sv[row * QK_PITCH + col] = make_uint4(0, 0, 0, 0);
    }
    __syncthreads();

    unsigned sq_u = smem_u32(&sq[win][0]), sk_u = smem_u32(sk), sv_u = smem_u32(sv);
    int w = w0 + win;

    // ---- S = q @ k^T ----
    float acc[8][4];
    #pragma unroll
    for (int a = 0; a < 8; ++a)
        #pragma unroll
        for (int c = 0; c < 4; ++c) acc[a][c] = 0.0f;
    {
        unsigned ah[2][4], bh[2][4][4];
        #pragma unroll
        for (int kt = 0; kt < 2; ++kt)
            LDSM4(ah[kt], sq_u + ((m0 + (lane & 15)) * QK_PITCH + kt * 16 + (lane >> 4) * 8) * 2);
        #pragma unroll
        for (int kt = 0; kt < 2; ++kt)
            #pragma unroll
            for (int nt = 0; nt < 4; ++nt)
                LDSM4(bh[kt][nt], sk_u + ((nt * 16 + (lane & 15)) * QK_PITCH + kt * 16 + (lane >> 4) * 8) * 2);
        #pragma unroll
        for (int kt = 0; kt < 2; ++kt)
            #pragma unroll
            for (int nt = 0; nt < 4; ++nt) {
                MMA_F16(acc[nt * 2 + 0], ah[kt], bh[kt][nt][0], bh[kt][nt][2]);
                MMA_F16(acc[nt * 2 + 1], ah[kt], bh[kt][nt][1], bh[kt][nt][3]);
            }
    }

    // ---- register softmax over rows i1, i2 ----
    int r = lane >> 2, c2 = (lane & 3) * 2;
    int i1 = m0 + r, i2 = i1 + 8;
    const fp16* bp = bmh + h * 2500;
    float v1[16], v2[16];
    #pragma unroll
    for (int nj = 0; nj < 8; ++nj) {
        int j0 = nj * 8 + c2;
        float b0 = 0.f, b1 = 0.f, b2 = 0.f, b3 = 0.f;
        if (j0 < 49) {
            if (i1 < 49) {
                __half2 bb = *(const __half2*)&bp[i1 * 50 + j0];
                b0 = __low2float(bb); b1 = __high2float(bb);
            }
            if (i2 < 49) {
                __half2 bb = *(const __half2*)&bp[i2 * 50 + j0];
                b2 = __low2float(bb); b3 = __high2float(bb);
            }
        }
        v1[nj * 2 + 0] = (j0     < 49) ? acc[nj][0] + b0 : -1e30f;
        v1[nj * 2 + 1] = (j0 + 1 < 49) ? acc[nj][1] + b1 : -1e30f;
        v2[nj * 2 + 0] = (j0     < 49) ? acc[nj][2] + b2 : -1e30f;
        v2[nj * 2 + 1] = (j0 + 1 < 49) ? acc[nj][3] + b3 : -1e30f;
    }
    float m1 = -1e30f, m2 = -1e30f;
    #pragma unroll
    for (int t = 0; t < 16; ++t) { m1 = fmaxf(m1, v1[t]); m2 = fmaxf(m2, v2[t]); }
    m1 = fmaxf(m1, __shfl_xor_sync(0xffffffffu, m1, 1));
    m1 = fmaxf(m1, __shfl_xor_sync(0xffffffffu, m1, 2));
    m2 = fmaxf(m2, __shfl_xor_sync(0xffffffffu, m2, 1));
    m2 = fmaxf(m2, __shfl_xor_sync(0xffffffffu, m2, 2));
    float s1 = 0.f, s2 = 0.f;
    #pragma unroll
    for (int t = 0; t < 16; ++t) {
        v1[t] = __expf(v1[t] - m1); s1 += v1[t];
        v2[t] = __expf(v2[t] - m2); s2 += v2[t];
    }
    s1 += __shfl_xor_sync(0xffffffffu, s1, 1);
    s1 += __shfl_xor_sync(0xffffffffu, s1, 2);
    s2 += __shfl_xor_sync(0xffffffffu, s2, 1);
    s2 += __shfl_xor_sync(0xffffffffu, s2, 2);
    float inv1 = 1.0f / s1, inv2 = 1.0f / s2;

    // ---- pack P directly into MMA A-fragments ----
    unsigned pa[4][4];
    #pragma unroll
    for (int kt = 0; kt < 4; ++kt) {
        __half2 t0 = __floats2half2_rn(v1[4 * kt + 0] * inv1, v1[4 * kt + 1] * inv1);
        __half2 t1 = __floats2half2_rn(v2[4 * kt + 0] * inv2, v2[4 * kt + 1] * inv2);
        __half2 t2 = __floats2half2_rn(v1[4 * kt + 2] * inv1, v1[4 * kt + 3] * inv1);
        __half2 t3 = __floats2half2_rn(v2[4 * kt + 2] * inv2, v2[4 * kt + 3] * inv2);
        pa[kt][0] = *(unsigned*)&t0;
        pa[kt][1] = *(unsigned*)&t1;
        pa[kt][2] = *(unsigned*)&t2;
        pa[kt][3] = *(unsigned*)&t3;
    }

    // ---- O = P @ V ----
    float oa[4][4];
    #pragma unroll
    for (int a = 0; a < 4; ++a)
        #pragma unroll
        for (int c = 0; c < 4; ++c) oa[a][c] = 0.0f;
    #pragma unroll
    for (int kt = 0; kt < 4; ++kt) {
        #pragma unroll
        for (int nt = 0; nt < 2; ++nt) {
            unsigned bh2[4];
            LDSM4T(bh2, sv_u + ((kt * 16 + (lane & 15)) * QK_PITCH + nt * 16 + (lane >> 4) * 8) * 2);
            MMA_F16(oa[nt * 2 + 0], pa[kt], bh2[0], bh2[1]);
            MMA_F16(oa[nt * 2 + 1], pa[kt], bh2[2], bh2[3]);
        }
    }
    #pragma unroll
    for (int nt = 0; nt < 4; ++nt) {
        int d = nt * 8 + c2;
        if (i1 < NWIN) {
            __half2 hp;
            hp.x = __float2half_rn(oa[nt][0]); hp.y = __float2half_rn(oa[nt][1]);
            *(__half2*)&ao[((size_t)w * NWIN + i1) * CDIM + h * HDIM + d] = hp;
        }
        if (i2 < NWIN) {
            __half2 hp;
            hp.x = __float2half_rn(oa[nt][2]); hp.y = __float2half_rn(oa[nt][3]);
            *(__half2*)&ao[((size_t)w * NWIN + i2) * CDIM + h * HDIM + d] = hp;
        }
    }
}

// ============================================================
// launch
// ============================================================
extern "C" void kernel_launch(void* const* d_in, const int* in_sizes, int n_in,
                              void* d_out, int out_size)
{
    (void)in_sizes; (void)n_in; (void)out_size;
    const float* x     = (const float*)d_in[0];
    const float* kv    = (const float*)d_in[1];
    const int*   rel   = (const int*)d_in[2];
    const float* g1    = (const float*)d_in[5];
    const float* b1    = (const float*)d_in[6];
    const float* Wqkv  = (const float*)d_in[7];
    const float* bqkv  = (const float*)d_in[8];
    const float* btab  = (const float*)d_in[9];
    const float* Wproj = (const float*)d_in[10];
    const float* bproj = (const float*)d_in[11];
    const float* g2    = (const float*)d_in[12];
    const float* b2    = (const float*)d_in[13];
    const float* Wfc1  = (const float*)d_in[14];
    const float* bfc1  = (const float*)d_in[15];
    const float* Wfc2  = (const float*)d_in[16];
    const float* bfc2  = (const float*)d_in[17];
    float* out = (float*)d_out;

    static fp16 *x1h = nullptr;
    static fp16 *hw, *qh, *ao, *h2, *mid, *wq, *wp, *w1, *w2, *kvh, *bmh;
    if (!x1h) {
        cudaGetSymbolAddress((void**)&x1h, g_x1h);
        cudaGetSymbolAddress((void**)&bmh, g_bmh);
        cudaGetSymbolAddress((void**)&hw,  g_hw);
        cudaGetSymbolAddress((void**)&qh,  g_qh);
        cudaGetSymbolAddress((void**)&ao,  g_ao);
        cudaGetSymbolAddress((void**)&h2,  g_h2);
        cudaGetSymbolAddress((void**)&mid, g_mid);
        cudaGetSymbolAddress((void**)&wq,  g_wq);
        cudaGetSymbolAddress((void**)&wp,  g_wp);
        cudaGetSymbolAddress((void**)&w1,  g_w1);
        cudaGetSymbolAddress((void**)&w2,  g_w2);
        cudaGetSymbolAddress((void**)&kvh, g_kvh);
        cudaFuncSetAttribute(mma_gemm<EPI_Q>,    cudaFuncAttributeMaxDynamicSharedMemorySize, SMEM_DYN);
        cudaFuncSetAttribute(mma_gemm<EPI_PROJ>, cudaFuncAttributeMaxDynamicSharedMemorySize, SMEM_DYN);
        cudaFuncSetAttribute(mma_gemm<EPI_GELU>, cudaFuncAttributeMaxDynamicSharedMemorySize, SMEM_DYN);
        cudaFuncSetAttribute(mma_gemm<EPI_FC2>,  cudaFuncAttributeMaxDynamicSharedMemorySize, SMEM_DYN);
    }

    const float qscale = 0.17677669529663687f;

    pre_kernel<<<PRE_GRID, 128>>>(x, g1, b1, hw,
                                  Wqkv, Wproj, Wfc1, Wfc2, kv, rel, btab,
                                  wq, wp, w1, w2, kvh, bmh);

    mma_gemm<EPI_Q><<<dim3(3, 392), 256, SMEM_DYN>>>(hw, wq, 384,
        bqkv, nullptr, qh, nullptr, nullptr, qscale);

    // 512 window-pairs x 12 heads = 6144 blocks, 2 windows each in parallel
    attn_tc<<<512 * NHEADS, 256>>>(qh, kvh, bmh, ao);

    mma_gemm<EPI_PROJ><<<dim3(3, 392), 256, SMEM_DYN>>>(ao, wp, 384,
        bproj, nullptr, x1h, x, nullptr, 0.0f);

    ln_kernel_h<<<MROWS, 128>>>(x1h, g2, b2, h2);

    mma_gemm<EPI_GELU><<<dim3(12, 392), 256, SMEM_DYN>>>(h2, w1, 384,
        bfc1, nullptr, mid, nullptr, nullptr, 0.0f);

    mma_gemm<EPI_FC2><<<dim3(3, 392), 256, SMEM_DYN>>>(mid, w2, 1536,
        bfc2, out, nullptr, nullptr, x1h, 0.0f);
}

// round 16
// speedup vs baseline: 1.3114x; 1.0084x over previous
#include <cuda_runtime.h>
#include <cuda_fp16.h>
#include <math.h>

// Problem constants
#define MROWS  50176
#define CDIM   384
#define HIDDEN 1536
#define NHEADS 12
#define HDIM   32
#define NWIN   49
#define BWIN   1024
#define KV_ELEMS (2 * 16 * NHEADS * NWIN * HDIM)   // 602112

typedef __half fp16;

// -------- scratch (device globals; no allocations allowed) --------
__device__ fp16 g_x1h[(size_t)MROWS * CDIM];
__device__ fp16 g_hw [(size_t)MROWS * CDIM];
__device__ fp16 g_qh [(size_t)MROWS * CDIM];
__device__ fp16 g_ao [(size_t)MROWS * CDIM];
__device__ fp16 g_h2 [(size_t)MROWS * CDIM];
__device__ fp16 g_mid[(size_t)MROWS * HIDDEN];
__device__ fp16 g_wq [384 * 384];
__device__ fp16 g_wp [384 * 384];
__device__ fp16 g_w1 [384 * 1536];
__device__ fp16 g_w2 [1536 * 384];
__device__ fp16 g_kvh[KV_ELEMS];
__device__ fp16 g_bmh[NHEADS * 50 * 50];   // fp16 bias matrix, pitch 50

// ================= PTX helpers =================
__device__ __forceinline__ unsigned smem_u32(const void* p) {
    unsigned a;
    asm("{ .reg .u64 t; cvta.to.shared.u64 t, %1; cvt.u32.u64 %0, t; }" : "=r"(a) : "l"(p));
    return a;
}
__device__ __forceinline__ void cp16(unsigned dst, const void* src) {
    asm volatile("cp.async.cg.shared.global [%0], [%1], 16;" :: "r"(dst), "l"(src) : "memory");
}
#define CP_COMMIT() asm volatile("cp.async.commit_group;" ::: "memory")
#define CP_WAIT(n)  asm volatile("cp.async.wait_group %0;" :: "n"(n) : "memory")

#define LDSM4(r, a)                                                                \
    asm volatile("ldmatrix.sync.aligned.m8n8.x4.shared.b16 {%0,%1,%2,%3}, [%4];"   \
        : "=r"((r)[0]), "=r"((r)[1]), "=r"((r)[2]), "=r"((r)[3]) : "r"(a))

#define LDSM4T(r, a)                                                               \
    asm volatile("ldmatrix.sync.aligned.m8n8.x4.trans.shared.b16 {%0,%1,%2,%3}, [%4];" \
        : "=r"((r)[0]), "=r"((r)[1]), "=r"((r)[2]), "=r"((r)[3]) : "r"(a))

#define MMA_F16(d, a, b0, b1)                                                      \
    asm volatile("mma.sync.aligned.m16n8k16.row.col.f32.f16.f16.f32 "              \
        "{%0,%1,%2,%3}, {%4,%5,%6,%7}, {%8,%9}, {%0,%1,%2,%3};"                    \
        : "+f"((d)[0]), "+f"((d)[1]), "+f"((d)[2]), "+f"((d)[3])                    \
        : "r"((a)[0]), "r"((a)[1]), "r"((a)[2]), "r"((a)[3]), "r"(b0), "r"(b1))

// ============================================================
// pre_kernel: LN1 (+window partition) fused with ALL conversions.
// ============================================================
#define WT_TILES 1440
#define KV_BLKS  588
#define BM_BLKS  226
#define PRE_GRID (MROWS + WT_TILES + KV_BLKS + BM_BLKS)

__global__ void pre_kernel(const float* __restrict__ x, const float* __restrict__ g,
                           const float* __restrict__ bb, fp16* __restrict__ oh,
                           const float* __restrict__ Wq, const float* __restrict__ Wp,
                           const float* __restrict__ W1, const float* __restrict__ W2,
                           const float* __restrict__ kv,
                           const int* __restrict__ rel, const float* __restrict__ btab,
                           fp16* __restrict__ oq, fp16* __restrict__ op,
                           fp16* __restrict__ o1, fp16* __restrict__ o2,
                           fp16* __restrict__ okv, fp16* __restrict__ bmh)
{
    __shared__ float tile[32][33];
    __shared__ float rs[4], rss[4], smean, sinv;

    int b = blockIdx.x;
    int tid = threadIdx.x;

    if (b < MROWS) {
        int w = b / NWIN, n = b % NWIN;
        int bimg = w >> 6, wy = (w >> 3) & 7, wx = w & 7;
        int iy = n / 7, ix = n % 7;
        size_t srow = (size_t)bimg * 3136 + (wy * 7 + iy) * 56 + (wx * 7 + ix);
        const float* xr = x + srow * CDIM;
        float v0 = xr[tid], v1 = xr[tid + 128], v2 = xr[tid + 256];
        float s = v0 + v1 + v2, ss = v0 * v0 + v1 * v1 + v2 * v2;
        #pragma unroll
        for (int o = 16; o; o >>= 1) {
            s  += __shfl_xor_sync(0xffffffffu, s,  o);
            ss += __shfl_xor_sync(0xffffffffu, ss, o);
        }
        int warp = tid >> 5, lane = tid & 31;
        if (lane == 0) { rs[warp] = s; rss[warp] = ss; }
        __syncthreads();
        if (tid == 0) {
            float S = rs[0] + rs[1] + rs[2] + rs[3];
            float SS = rss[0] + rss[1] + rss[2] + rss[3];
            float m = S * (1.0f / 384.0f);
            smean = m;
            sinv = rsqrtf(SS * (1.0f / 384.0f) - m * m + 1e-5f);
        }
        __syncthreads();
        size_t orow = (size_t)b * CDIM;
        #pragma unroll
        for (int c = 0; c < 3; ++c) {
            float vv = (c == 0 ? v0 : c == 1 ? v1 : v2);
            int col = tid + c * 128;
            oh[orow + col] = __float2half_rn((vv - smean) * sinv * g[col] + bb[col]);
        }
        return;
    }
    b -= MROWS;
    if (b < WT_TILES) {
        const float* W; fp16* o; int Kd, ld, tiles_n, tt;
        if (b < 144)      { W = Wq; o = oq; Kd = 384;  ld = 1152; tiles_n = 12; tt = b; }
        else if (b < 288) { W = Wp; o = op; Kd = 384;  ld = 384;  tiles_n = 12; tt = b - 144; }
        else if (b < 864) { W = W1; o = o1; Kd = 384;  ld = 1536; tiles_n = 48; tt = b - 288; }
        else              { W = W2; o = o2; Kd = 1536; ld = 384;  tiles_n = 12; tt = b - 864; }
        int tk = tt / tiles_n, tn = tt % tiles_n;
        int k0 = tk * 32, n0 = tn * 32;
        int tx = tid & 31, ty = tid >> 5;
        #pragma unroll
        for (int i = 0; i < 8; ++i)
            tile[ty + 4 * i][tx] = W[(size_t)(k0 + ty + 4 * i) * ld + n0 + tx];
        __syncthreads();
        #pragma unroll
        for (int i = 0; i < 8; ++i)
            o[(size_t)(n0 + ty + 4 * i) * Kd + k0 + tx] = __float2half_rn(tile[tx][ty + 4 * i]);
        return;
    }
    b -= WT_TILES;
    if (b < KV_BLKS) {
        int base = b * 1024 + tid;
        #pragma unroll
        for (int i = 0; i < 8; ++i) {
            int idx = base + i * 128;
            if (idx < KV_ELEMS) okv[idx] = __float2half_rn(kv[idx]);
        }
        return;
    }
    b -= KV_BLKS;
    {
        int t = b * 128 + tid;
        if (t < NHEADS * NWIN * NWIN) {
            int h = t / (NWIN * NWIN), ij = t % (NWIN * NWIN);
            int i = ij / NWIN, j = ij - i * NWIN;
            bmh[h * 2500 + i * 50 + j] = __float2half_rn(btab[rel[ij] * NHEADS + h]);
        }
    }
}

// ============================================================
// LayerNorm (fp16 input rows) -> fp16  (R12 proven version)
// ============================================================
__global__ void ln_kernel_h(const fp16* __restrict__ xin, const float* __restrict__ g,
                            const float* __restrict__ bb, fp16* __restrict__ oh)
{
    int r = blockIdx.x;
    const fp16* xr = xin + (size_t)r * CDIM;
    int tid = threadIdx.x;
    float v0 = __half2float(xr[tid]);
    float v1 = __half2float(xr[tid + 128]);
    float v2 = __half2float(xr[tid + 256]);
    float s = v0 + v1 + v2, ss = v0 * v0 + v1 * v1 + v2 * v2;
    #pragma unroll
    for (int o = 16; o; o >>= 1) {
        s  += __shfl_xor_sync(0xffffffffu, s,  o);
        ss += __shfl_xor_sync(0xffffffffu, ss, o);
    }
    __shared__ float rs[4], rss[4], smean, sinv;
    int warp = tid >> 5, lane = tid & 31;
    if (lane == 0) { rs[warp] = s; rss[warp] = ss; }
    __syncthreads();
    if (tid == 0) {
        float S = rs[0] + rs[1] + rs[2] + rs[3];
        float SS = rss[0] + rss[1] + rss[2] + rss[3];
        float m = S * (1.0f / 384.0f);
        smean = m;
        sinv = rsqrtf(SS * (1.0f / 384.0f) - m * m + 1e-5f);
    }
    __syncthreads();
    size_t orow = (size_t)r * CDIM;
    #pragma unroll
    for (int c = 0; c < 3; ++c) {
        float vv = (c == 0 ? v0 : c == 1 ? v1 : v2);
        int col = tid + c * 128;
        oh[orow + col] = __float2half_rn((vv - smean) * sinv * g[col] + bb[col]);
    }
}

// ============================================================
// Big fp16 GEMM (fc1/fc2): 128x128, KC=64, 3-stage (R12 proven)
// ============================================================
enum { EPI_Q = 0, EPI_PROJ = 1, EPI_GELU = 2, EPI_FC2 = 3 };
#define TILE_B   18432
#define STAGE_B  36864
#define NSTAGE   3
#define SMEM_DYN (NSTAGE * STAGE_B)   // 110592

template <int EPI>
__global__ void __launch_bounds__(256, 2)
mma_gemm(const fp16* __restrict__ Am, const fp16* __restrict__ Bm,
         int K, const float* __restrict__ bias,
         float* __restrict__ Cf, fp16* __restrict__ Ch,
         const float* __restrict__ resid, const fp16* __restrict__ residh,
         float scale)
{
    extern __shared__ char sm_raw[];
    unsigned sbase = smem_u32(sm_raw);

    int tid = threadIdx.x, wid = tid >> 5, lane = tid & 31;
    int bm = blockIdx.y * 128, bn = blockIdx.x * 128;
    int m0 = (wid & 3) * 32, n0 = (wid >> 2) * 64;

    int rowL[8], chL[8], tileL[8];
    #pragma unroll
    for (int t = 0; t < 8; ++t) {
        int item = tid + t * 256;
        tileL[t] = item >> 10;
        int rem = item & 1023;
        rowL[t] = rem >> 3; chL[t] = rem & 7;
    }

    auto load_stage = [&](int stage, int k0) {
        unsigned db = sbase + stage * STAGE_B;
        #pragma unroll
        for (int t = 0; t < 8; ++t) {
            const fp16* src = (tileL[t] ? Bm : Am)
                + (size_t)((tileL[t] ? bn : bm) + rowL[t]) * K + k0 + chL[t] * 8;
            cp16(db + tileL[t] * TILE_B + rowL[t] * 144 + chL[t] * 16, src);
        }
        CP_COMMIT();
    };

    float acc[2][8][4];
    #pragma unroll
    for (int a = 0; a < 2; ++a)
        #pragma unroll
        for (int b = 0; b < 8; ++b)
            #pragma unroll
            for (int c = 0; c < 4; ++c) acc[a][b][c] = 0.0f;

    int niter = K >> 6;
    load_stage(0, 0);
    load_stage(1, 64);

    unsigned a_base[2], b_base[4];
    #pragma unroll
    for (int mt = 0; mt < 2; ++mt)
        a_base[mt] = (m0 + mt * 16 + (lane & 15)) * 144 + (lane >> 4) * 16;
    #pragma unroll
    for (int nt = 0; nt < 4; ++nt)
        b_base[nt] = TILE_B + (n0 + nt * 16 + (lane & 15)) * 144 + (lane >> 4) * 16;

    int st = 0;
    for (int it = 0; it < niter; ++it) {
        CP_WAIT(1);
        __syncthreads();

        if (it + 2 < niter) {
            int pst = st + 2; if (pst >= 3) pst -= 3;
            load_stage(pst, (it + 2) * 64);
        } else CP_COMMIT();

        unsigned base = sbase + st * STAGE_B;

        #pragma unroll
        for (int kp = 0; kp < 2; ++kp) {
            unsigned koff = kp * 64;
            unsigned ah[2][2][4], bh[2][4][4];
            #pragma unroll
            for (int ks = 0; ks < 2; ++ks)
                #pragma unroll
                for (int mt = 0; mt < 2; ++mt)
                    LDSM4(ah[ks][mt], base + a_base[mt] + koff + ks * 32);
            #pragma unroll
            for (int ks = 0; ks < 2; ++ks)
                #pragma unroll
                for (int nt = 0; nt < 4; ++nt)
                    LDSM4(bh[ks][nt], base + b_base[nt] + koff + ks * 32);

            #pragma unroll
            for (int ks = 0; ks < 2; ++ks)
                #pragma unroll
                for (int nt = 0; nt < 4; ++nt)
                    #pragma unroll
                    for (int mt = 0; mt < 2; ++mt) {
                        MMA_F16(acc[mt][nt * 2 + 0], ah[ks][mt], bh[ks][nt][0], bh[ks][nt][2]);
                        MMA_F16(acc[mt][nt * 2 + 1], ah[ks][mt], bh[ks][nt][1], bh[ks][nt][3]);
                    }
        }
        if (++st >= 3) st = 0;
    }

    int r_in = lane >> 2, c_in = (lane & 3) * 2;
    #pragma unroll
    for (int mt = 0; mt < 2; ++mt) {
        #pragma unroll
        for (int j = 0; j < 8; ++j) {
            int col = bn + n0 + j * 8 + c_in;
            #pragma unroll
            for (int hf = 0; hf < 2; ++hf) {
                int row = bm + m0 + mt * 16 + r_in + hf * 8;
                float v0 = acc[mt][j][hf * 2 + 0];
                float v1 = acc[mt][j][hf * 2 + 1];
                if (EPI == EPI_GELU) {
                    float a0 = v0 + bias[col], a1 = v1 + bias[col + 1];
                    float g0 = 0.5f * a0 * (1.0f + erff(a0 * 0.70710678118654752f));
                    float g1 = 0.5f * a1 * (1.0f + erff(a1 * 0.70710678118654752f));
                    __half2 hp;
                    hp.x = __float2half_rn(g0); hp.y = __float2half_rn(g1);
                    *(__half2*)&Ch[(size_t)row * HIDDEN + col] = hp;
                } else {  // EPI_FC2
                    size_t o = (size_t)row * CDIM + col;
                    __half2 rh = *(const __half2*)&residh[o];
                    *(float2*)&Cf[o] = make_float2(v0 + bias[col] + __low2float(rh),
                                                   v1 + bias[col + 1] + __high2float(rh));
                }
            }
        }
    }
}

// ============================================================
// Small-tile GEMM for K=384 layers (q, proj): 64x128 tile,
// KC=32, 4-stage, 3 CTAs/SM target (acc 32/thread).
// Warp grid: 2 m-warps x 4 n-warps, each 32x32.
// ============================================================
#define S_A_B    5120            // 64 rows * 80B
#define S_STAGE  15360           // + 128 rows * 80B for B
#define SMEM_S   (4 * S_STAGE)   // 61440

template <int EPI>
__global__ void __launch_bounds__(256, 3)
mma_gemm_s(const fp16* __restrict__ Am, const fp16* __restrict__ Bm,
           const float* __restrict__ bias, fp16* __restrict__ Ch,
           const float* __restrict__ resid, float scale)
{
    extern __shared__ char sm_raw[];
    unsigned sbase = smem_u32(sm_raw);

    int tid = threadIdx.x, wid = tid >> 5, lane = tid & 31;
    int bm = blockIdx.y * 64, bn = blockIdx.x * 128;
    int m0 = (wid & 1) * 32, n0 = (wid >> 1) * 32;

    const int K = 384;

    // 3 cp.async per thread per stage: 256 A-chunks + 512 B-chunks
    auto load_stage = [&](int stage, int k0) {
        unsigned db = sbase + stage * S_STAGE;
        #pragma unroll
        for (int t = 0; t < 3; ++t) {
            int item = tid + t * 256;
            int isB = item >= 256;
            int rem = isB ? item - 256 : item;
            int row = rem >> 2, ch = rem & 3;
            const fp16* src = (isB ? Bm : Am)
                + (size_t)((isB ? bn : bm) + row) * K + k0 + ch * 8;
            cp16(db + isB * S_A_B + row * 80 + ch * 16, src);
        }
        CP_COMMIT();
    };

    float acc[2][4][4];
    #pragma unroll
    for (int a = 0; a < 2; ++a)
        #pragma unroll
        for (int b = 0; b < 4; ++b)
            #pragma unroll
            for (int c = 0; c < 4; ++c) acc[a][b][c] = 0.0f;

    const int niter = 12;       // 384 / 32
    load_stage(0, 0);
    load_stage(1, 32);
    load_stage(2, 64);

    unsigned a_base[2], b_base[2];
    #pragma unroll
    for (int mt = 0; mt < 2; ++mt)
        a_base[mt] = (m0 + mt * 16 + (lane & 15)) * 80 + (lane >> 4) * 16;
    #pragma unroll
    for (int nt = 0; nt < 2; ++nt)
        b_base[nt] = S_A_B + (n0 + nt * 16 + (lane & 15)) * 80 + (lane >> 4) * 16;

    for (int it = 0; it < niter; ++it) {
        CP_WAIT(2);
        __syncthreads();

        if (it + 3 < niter) load_stage((it + 3) & 3, (it + 3) * 32);
        else CP_COMMIT();

        unsigned base = sbase + (it & 3) * S_STAGE;

        unsigned ah[2][2][4], bh[2][2][4];
        #pragma unroll
        for (int ks = 0; ks < 2; ++ks) {
            #pragma unroll
            for (int mt = 0; mt < 2; ++mt) LDSM4(ah[ks][mt], base + a_base[mt] + ks * 32);
            #pragma unroll
            for (int nt = 0; nt < 2; ++nt) LDSM4(bh[ks][nt], base + b_base[nt] + ks * 32);
        }
        #pragma unroll
        for (int ks = 0; ks < 2; ++ks)
            #pragma unroll
            for (int nt = 0; nt < 2; ++nt)
                #pragma unroll
                for (int mt = 0; mt < 2; ++mt) {
                    MMA_F16(acc[mt][nt * 2 + 0], ah[ks][mt], bh[ks][nt][0], bh[ks][nt][2]);
                    MMA_F16(acc[mt][nt * 2 + 1], ah[ks][mt], bh[ks][nt][1], bh[ks][nt][3]);
                }
    }

    int r_in = lane >> 2, c_in = (lane & 3) * 2;
    #pragma unroll
    for (int mt = 0; mt < 2; ++mt) {
        #pragma unroll
        for (int j = 0; j < 4; ++j) {
            int col = bn + n0 + j * 8 + c_in;
            #pragma unroll
            for (int hf = 0; hf < 2; ++hf) {
                int row = bm + m0 + mt * 16 + r_in + hf * 8;
                float v0 = acc[mt][j][hf * 2 + 0];
                float v1 = acc[mt][j][hf * 2 + 1];
                if (EPI == EPI_Q) {
                    int w = row / NWIN, n = row % NWIN;
                    int hd = col >> 5, d = col & 31;
                    __half2 hp;
                    hp.x = __float2half_rn((v0 + bias[col]) * scale);
                    hp.y = __float2half_rn((v1 + bias[col + 1]) * scale);
                    *(__half2*)&Ch[((size_t)(w * NHEADS + hd) * NWIN + n) * HDIM + d] = hp;
                } else {  // EPI_PROJ
                    int w = row / NWIN, n = row % NWIN;
                    int bimg = w >> 6, wy = (w >> 3) & 7, wx = w & 7;
                    int iy = n / 7, ix = n % 7;
                    size_t o = ((size_t)bimg * 3136 + (wy * 7 + iy) * 56 + (wx * 7 + ix)) * CDIM + col;
                    float2 r2 = *(const float2*)&resid[o];
                    __half2 hp;
                    hp.x = __float2half_rn(v0 + bias[col] + r2.x);
                    hp.y = __float2half_rn(v1 + bias[col + 1] + r2.y);
                    *(__half2*)&Ch[o] = hp;
                }
            }
        }
    }
}

// ============================================================
// Tensor-core windowed attention (R12-exact: per-window,
// register softmax, one barrier, V row-major + trans ldmatrix)
// ============================================================
#define QK_PITCH 40

__global__ void __launch_bounds__(128)
attn_tc(const fp16* __restrict__ q, const fp16* __restrict__ kvh,
        const fp16* __restrict__ bmh, fp16* __restrict__ ao)
{
    __shared__ fp16 sq[64 * QK_PITCH];
    __shared__ fp16 sk[64 * QK_PITCH];
    __shared__ fp16 sv[64 * QK_PITCH];

    int blk = blockIdx.x;
    int w = blk / NHEADS, h = blk - w * NHEADS;
    int bimg = w >> 6;
    int tid = threadIdx.x, wid = tid >> 5, lane = tid & 31;

    const fp16* qp = q + (size_t)blk * (NWIN * HDIM);
    const fp16* kp = kvh + (size_t)(bimg * NHEADS + h) * (NWIN * HDIM);
    const fp16* vp = kp + (size_t)16 * NHEADS * NWIN * HDIM;

    for (int t = tid; t < 196; t += 128) {
        int row = t >> 2, col = (t & 3) * 8;
        *(uint4*)&sq[row * QK_PITCH + col] = ((const uint4*)qp)[t];
        *(uint4*)&sk[row * QK_PITCH + col] = ((const uint4*)kp)[t];
        *(uint4*)&sv[row * QK_PITCH + col] = ((const uint4*)vp)[t];
    }
    for (int t = tid; t < 60; t += 128) {
        int row = 49 + (t >> 2), col = (t & 3) * 8;
        *(uint4*)&sv[row * QK_PITCH + col] = make_uint4(0, 0, 0, 0);
    }
    __syncthreads();

    unsigned sq_u = smem_u32(sq), sk_u = smem_u32(sk), sv_u = smem_u32(sv);
    int m0 = wid * 16;

    float acc[8][4];
    #pragma unroll
    for (int a = 0; a < 8; ++a)
        #pragma unroll
        for (int c = 0; c < 4; ++c) acc[a][c] = 0.0f;
    {
        unsigned ah[2][4], bh[2][4][4];
        #pragma unroll
        for (int kt = 0; kt < 2; ++kt)
            LDSM4(ah[kt], sq_u + ((m0 + (lane & 15)) * QK_PITCH + kt * 16 + (lane >> 4) * 8) * 2);
        #pragma unroll
        for (int kt = 0; kt < 2; ++kt)
            #pragma unroll
            for (int nt = 0; nt < 4; ++nt)
                LDSM4(bh[kt][nt], sk_u + ((nt * 16 + (lane & 15)) * QK_PITCH + kt * 16 + (lane >> 4) * 8) * 2);
        #pragma unroll
        for (int kt = 0; kt < 2; ++kt)
            #pragma unroll
            for (int nt = 0; nt < 4; ++nt) {
                MMA_F16(acc[nt * 2 + 0], ah[kt], bh[kt][nt][0], bh[kt][nt][2]);
                MMA_F16(acc[nt * 2 + 1], ah[kt], bh[kt][nt][1], bh[kt][nt][3]);
            }
    }

    int r = lane >> 2, c2 = (lane & 3) * 2;
    int i1 = m0 + r, i2 = i1 + 8;
    const fp16* bp = bmh + h * 2500;
    float v1[16], v2[16];
    #pragma unroll
    for (int nj = 0; nj < 8; ++nj) {
        int j0 = nj * 8 + c2;
        float b0 = 0.f, b1 = 0.f, b2 = 0.f, b3 = 0.f;
        if (j0 < 49) {
            if (i1 < 49) {
                __half2 bb = *(const __half2*)&bp[i1 * 50 + j0];
                b0 = __low2float(bb); b1 = __high2float(bb);
            }
            if (i2 < 49) {
                __half2 bb = *(const __half2*)&bp[i2 * 50 + j0];
                b2 = __low2float(bb); b3 = __high2float(bb);
            }
        }
        v1[nj * 2 + 0] = (j0     < 49) ? acc[nj][0] + b0 : -1e30f;
        v1[nj * 2 + 1] = (j0 + 1 < 49) ? acc[nj][1] + b1 : -1e30f;
        v2[nj * 2 + 0] = (j0     < 49) ? acc[nj][2] + b2 : -1e30f;
        v2[nj * 2 + 1] = (j0 + 1 < 49) ? acc[nj][3] + b3 : -1e30f;
    }
    float m1 = -1e30f, m2 = -1e30f;
    #pragma unroll
    for (int t = 0; t < 16; ++t) { m1 = fmaxf(m1, v1[t]); m2 = fmaxf(m2, v2[t]); }
    m1 = fmaxf(m1, __shfl_xor_sync(0xffffffffu, m1, 1));
    m1 = fmaxf(m1, __shfl_xor_sync(0xffffffffu, m1, 2));
    m2 = fmaxf(m2, __shfl_xor_sync(0xffffffffu, m2, 1));
    m2 = fmaxf(m2, __shfl_xor_sync(0xffffffffu, m2, 2));
    float s1 = 0.f, s2 = 0.f;
    #pragma unroll
    for (int t = 0; t < 16; ++t) {
        v1[t] = __expf(v1[t] - m1); s1 += v1[t];
        v2[t] = __expf(v2[t] - m2); s2 += v2[t];
    }
    s1 += __shfl_xor_sync(0xffffffffu, s1, 1);
    s1 += __shfl_xor_sync(0xffffffffu, s1, 2);
    s2 += __shfl_xor_sync(0xffffffffu, s2, 1);
    s2 += __shfl_xor_sync(0xffffffffu, s2, 2);
    float inv1 = 1.0f / s1, inv2 = 1.0f / s2;

    unsigned pa[4][4];
    #pragma unroll
    for (int kt = 0; kt < 4; ++kt) {
        __half2 t0 = __floats2half2_rn(v1[4 * kt + 0] * inv1, v1[4 * kt + 1] * inv1);
        __half2 t1 = __floats2half2_rn(v2[4 * kt + 0] * inv2, v2[4 * kt + 1] * inv2);
        __half2 t2 = __floats2half2_rn(v1[4 * kt + 2] * inv1, v1[4 * kt + 3] * inv1);
        __half2 t3 = __floats2half2_rn(v2[4 * kt + 2] * inv2, v2[4 * kt + 3] * inv2);
        pa[kt][0] = *(unsigned*)&t0;
        pa[kt][1] = *(unsigned*)&t1;
        pa[kt][2] = *(unsigned*)&t2;
        pa[kt][3] = *(unsigned*)&t3;
    }

    float oa[4][4];
    #pragma unroll
    for (int a = 0; a < 4; ++a)
        #pragma unroll
        for (int c = 0; c < 4; ++c) oa[a][c] = 0.0f;
    #pragma unroll
    for (int kt = 0; kt < 4; ++kt) {
        #pragma unroll
        for (int nt = 0; nt < 2; ++nt) {
            unsigned bh2[4];
            LDSM4T(bh2, sv_u + ((kt * 16 + (lane & 15)) * QK_PITCH + nt * 16 + (lane >> 4) * 8) * 2);
            MMA_F16(oa[nt * 2 + 0], pa[kt], bh2[0], bh2[1]);
            MMA_F16(oa[nt * 2 + 1], pa[kt], bh2[2], bh2[3]);
        }
    }
    #pragma unroll
    for (int nt = 0; nt < 4; ++nt) {
        int d = nt * 8 + c2;
        if (i1 < NWIN) {
            __half2 hp;
            hp.x = __float2half_rn(oa[nt][0]); hp.y = __float2half_rn(oa[nt][1]);
            *(__half2*)&ao[((size_t)w * NWIN + i1) * CDIM + h * HDIM + d] = hp;
        }
        if (i2 < NWIN) {
            __half2 hp;
            hp.x = __float2half_rn(oa[nt][2]); hp.y = __float2half_rn(oa[nt][3]);
            *(__half2*)&ao[((size_t)w * NWIN + i2) * CDIM + h * HDIM + d] = hp;
        }
    }
}

// ============================================================
// launch
// ============================================================
extern "C" void kernel_launch(void* const* d_in, const int* in_sizes, int n_in,
                              void* d_out, int out_size)
{
    (void)in_sizes; (void)n_in; (void)out_size;
    const float* x     = (const float*)d_in[0];
    const float* kv    = (const float*)d_in[1];
    const int*   rel   = (const int*)d_in[2];
    const float* g1    = (const float*)d_in[5];
    const float* b1    = (const float*)d_in[6];
    const float* Wqkv  = (const float*)d_in[7];
    const float* bqkv  = (const float*)d_in[8];
    const float* btab  = (const float*)d_in[9];
    const float* Wproj = (const float*)d_in[10];
    const float* bproj = (const float*)d_in[11];
    const float* g2    = (const float*)d_in[12];
    const float* b2    = (const float*)d_in[13];
    const float* Wfc1  = (const float*)d_in[14];
    const float* bfc1  = (const float*)d_in[15];
    const float* Wfc2  = (const float*)d_in[16];
    const float* bfc2  = (const float*)d_in[17];
    float* out = (float*)d_out;

    static fp16 *x1h = nullptr;
    static fp16 *hw, *qh, *ao, *h2, *mid, *wq, *wp, *w1, *w2, *kvh, *bmh;
    if (!x1h) {
        cudaGetSymbolAddress((void**)&x1h, g_x1h);
        cudaGetSymbolAddress((void**)&bmh, g_bmh);
        cudaGetSymbolAddress((void**)&hw,  g_hw);
        cudaGetSymbolAddress((void**)&qh,  g_qh);
        cudaGetSymbolAddress((void**)&ao,  g_ao);
        cudaGetSymbolAddress((void**)&h2,  g_h2);
        cudaGetSymbolAddress((void**)&mid, g_mid);
        cudaGetSymbolAddress((void**)&wq,  g_wq);
        cudaGetSymbolAddress((void**)&wp,  g_wp);
        cudaGetSymbolAddress((void**)&w1,  g_w1);
        cudaGetSymbolAddress((void**)&w2,  g_w2);
        cudaGetSymbolAddress((void**)&kvh, g_kvh);
        cudaFuncSetAttribute(mma_gemm<EPI_GELU>, cudaFuncAttributeMaxDynamicSharedMemorySize, SMEM_DYN);
        cudaFuncSetAttribute(mma_gemm<EPI_FC2>,  cudaFuncAttributeMaxDynamicSharedMemorySize, SMEM_DYN);
        cudaFuncSetAttribute(mma_gemm_s<EPI_Q>,    cudaFuncAttributeMaxDynamicSharedMemorySize, SMEM_S);
        cudaFuncSetAttribute(mma_gemm_s<EPI_PROJ>, cudaFuncAttributeMaxDynamicSharedMemorySize, SMEM_S);
    }

    const float qscale = 0.17677669529663687f;

    pre_kernel<<<PRE_GRID, 128>>>(x, g1, b1, hw,
                                  Wqkv, Wproj, Wfc1, Wfc2, kv, rel, btab,
                                  wq, wp, w1, w2, kvh, bmh);

    // q GEMM: small-tile latency-optimized (64x128, 3 CTAs/SM)
    mma_gemm_s<EPI_Q><<<dim3(3, 784), 256, SMEM_S>>>(hw, wq,
        bqkv, qh, nullptr, qscale);

    attn_tc<<<BWIN * NHEADS, 128>>>(qh, kvh, bmh, ao);

    // proj + window_reverse + residual(x fp32) -> x1 fp16
    mma_gemm_s<EPI_PROJ><<<dim3(3, 784), 256, SMEM_S>>>(ao, wp,
        bproj, x1h, x, 0.0f);

    ln_kernel_h<<<MROWS, 128>>>(x1h, g2, b2, h2);

    mma_gemm<EPI_GELU><<<dim3(12, 392), 256, SMEM_DYN>>>(h2, w1, 384,
        bfc1, nullptr, mid, nullptr, nullptr, 0.0f);

    mma_gemm<EPI_FC2><<<dim3(3, 392), 256, SMEM_DYN>>>(mid, w2, 1536,
        bfc2, out, nullptr, nullptr, x1h, 0.0f);
}

// round 17
// speedup vs baseline: 1.3191x; 1.0059x over previous
#include <cuda_runtime.h>
#include <cuda_fp16.h>
#include <math.h>

// Problem constants
#define MROWS  50176
#define CDIM   384
#define HIDDEN 1536
#define NHEADS 12
#define HDIM   32
#define NWIN   49
#define BWIN   1024
#define KV_ELEMS (2 * 16 * NHEADS * NWIN * HDIM)   // 602112

typedef __half fp16;

// -------- scratch (device globals; no allocations allowed) --------
__device__ fp16 g_x1h[(size_t)MROWS * CDIM];
__device__ fp16 g_hw [(size_t)MROWS * CDIM];
__device__ fp16 g_qh [(size_t)MROWS * CDIM];
__device__ fp16 g_ao [(size_t)MROWS * CDIM];
__device__ fp16 g_h2 [(size_t)MROWS * CDIM];
__device__ fp16 g_mid[(size_t)MROWS * HIDDEN];
__device__ fp16 g_wq [384 * 384];
__device__ fp16 g_wp [384 * 384];
__device__ fp16 g_w1 [384 * 1536];
__device__ fp16 g_w2 [1536 * 384];
__device__ fp16 g_kvh[KV_ELEMS];
__device__ fp16 g_bmh[NHEADS * 50 * 50];   // fp16 bias matrix, pitch 50

// ================= PTX helpers =================
__device__ __forceinline__ unsigned smem_u32(const void* p) {
    unsigned a;
    asm("{ .reg .u64 t; cvta.to.shared.u64 t, %1; cvt.u32.u64 %0, t; }" : "=r"(a) : "l"(p));
    return a;
}
__device__ __forceinline__ void cp16(unsigned dst, const void* src) {
    asm volatile("cp.async.cg.shared.global [%0], [%1], 16;" :: "r"(dst), "l"(src) : "memory");
}
#define CP_COMMIT() asm volatile("cp.async.commit_group;" ::: "memory")
#define CP_WAIT(n)  asm volatile("cp.async.wait_group %0;" :: "n"(n) : "memory")

#define LDSM4(r, a)                                                                \
    asm volatile("ldmatrix.sync.aligned.m8n8.x4.shared.b16 {%0,%1,%2,%3}, [%4];"   \
        : "=r"((r)[0]), "=r"((r)[1]), "=r"((r)[2]), "=r"((r)[3]) : "r"(a))

#define LDSM4T(r, a)                                                               \
    asm volatile("ldmatrix.sync.aligned.m8n8.x4.trans.shared.b16 {%0,%1,%2,%3}, [%4];" \
        : "=r"((r)[0]), "=r"((r)[1]), "=r"((r)[2]), "=r"((r)[3]) : "r"(a))

#define MMA_F16(d, a, b0, b1)                                                      \
    asm volatile("mma.sync.aligned.m16n8k16.row.col.f32.f16.f16.f32 "              \
        "{%0,%1,%2,%3}, {%4,%5,%6,%7}, {%8,%9}, {%0,%1,%2,%3};"                    \
        : "+f"((d)[0]), "+f"((d)[1]), "+f"((d)[2]), "+f"((d)[3])                    \
        : "r"((a)[0]), "r"((a)[1]), "r"((a)[2]), "r"((a)[3]), "r"(b0), "r"(b1))

// ============================================================
// pre_kernel: LN1 (+window partition) fused with ALL conversions.
// ============================================================
#define WT_TILES 1440
#define KV_BLKS  588
#define BM_BLKS  226
#define PRE_GRID (MROWS + WT_TILES + KV_BLKS + BM_BLKS)

__global__ void pre_kernel(const float* __restrict__ x, const float* __restrict__ g,
                           const float* __restrict__ bb, fp16* __restrict__ oh,
                           const float* __restrict__ Wq, const float* __restrict__ Wp,
                           const float* __restrict__ W1, const float* __restrict__ W2,
                           const float* __restrict__ kv,
                           const int* __restrict__ rel, const float* __restrict__ btab,
                           fp16* __restrict__ oq, fp16* __restrict__ op,
                           fp16* __restrict__ o1, fp16* __restrict__ o2,
                           fp16* __restrict__ okv, fp16* __restrict__ bmh)
{
    __shared__ float tile[32][33];
    __shared__ float rs[4], rss[4], smean, sinv;

    int b = blockIdx.x;
    int tid = threadIdx.x;

    if (b < MROWS) {
        int w = b / NWIN, n = b % NWIN;
        int bimg = w >> 6, wy = (w >> 3) & 7, wx = w & 7;
        int iy = n / 7, ix = n % 7;
        size_t srow = (size_t)bimg * 3136 + (wy * 7 + iy) * 56 + (wx * 7 + ix);
        const float* xr = x + srow * CDIM;
        float v0 = xr[tid], v1 = xr[tid + 128], v2 = xr[tid + 256];
        float s = v0 + v1 + v2, ss = v0 * v0 + v1 * v1 + v2 * v2;
        #pragma unroll
        for (int o = 16; o; o >>= 1) {
            s  += __shfl_xor_sync(0xffffffffu, s,  o);
            ss += __shfl_xor_sync(0xffffffffu, ss, o);
        }
        int warp = tid >> 5, lane = tid & 31;
        if (lane == 0) { rs[warp] = s; rss[warp] = ss; }
        __syncthreads();
        if (tid == 0) {
            float S = rs[0] + rs[1] + rs[2] + rs[3];
            float SS = rss[0] + rss[1] + rss[2] + rss[3];
            float m = S * (1.0f / 384.0f);
            smean = m;
            sinv = rsqrtf(SS * (1.0f / 384.0f) - m * m + 1e-5f);
        }
        __syncthreads();
        size_t orow = (size_t)b * CDIM;
        #pragma unroll
        for (int c = 0; c < 3; ++c) {
            float vv = (c == 0 ? v0 : c == 1 ? v1 : v2);
            int col = tid + c * 128;
            oh[orow + col] = __float2half_rn((vv - smean) * sinv * g[col] + bb[col]);
        }
        return;
    }
    b -= MROWS;
    if (b < WT_TILES) {
        const float* W; fp16* o; int Kd, ld, tiles_n, tt;
        if (b < 144)      { W = Wq; o = oq; Kd = 384;  ld = 1152; tiles_n = 12; tt = b; }
        else if (b < 288) { W = Wp; o = op; Kd = 384;  ld = 384;  tiles_n = 12; tt = b - 144; }
        else if (b < 864) { W = W1; o = o1; Kd = 384;  ld = 1536; tiles_n = 48; tt = b - 288; }
        else              { W = W2; o = o2; Kd = 1536; ld = 384;  tiles_n = 12; tt = b - 864; }
        int tk = tt / tiles_n, tn = tt % tiles_n;
        int k0 = tk * 32, n0 = tn * 32;
        int tx = tid & 31, ty = tid >> 5;
        #pragma unroll
        for (int i = 0; i < 8; ++i)
            tile[ty + 4 * i][tx] = W[(size_t)(k0 + ty + 4 * i) * ld + n0 + tx];
        __syncthreads();
        #pragma unroll
        for (int i = 0; i < 8; ++i)
            o[(size_t)(n0 + ty + 4 * i) * Kd + k0 + tx] = __float2half_rn(tile[tx][ty + 4 * i]);
        return;
    }
    b -= WT_TILES;
    if (b < KV_BLKS) {
        int base = b * 1024 + tid;
        #pragma unroll
        for (int i = 0; i < 8; ++i) {
            int idx = base + i * 128;
            if (idx < KV_ELEMS) okv[idx] = __float2half_rn(kv[idx]);
        }
        return;
    }
    b -= KV_BLKS;
    {
        int t = b * 128 + tid;
        if (t < NHEADS * NWIN * NWIN) {
            int h = t / (NWIN * NWIN), ij = t % (NWIN * NWIN);
            int i = ij / NWIN, j = ij - i * NWIN;
            bmh[h * 2500 + i * 50 + j] = __float2half_rn(btab[rel[ij] * NHEADS + h]);
        }
    }
}

// ============================================================
// LayerNorm (fp16 input rows) -> fp16
// ============================================================
__global__ void ln_kernel_h(const fp16* __restrict__ xin, const float* __restrict__ g,
                            const float* __restrict__ bb, fp16* __restrict__ oh)
{
    int r = blockIdx.x;
    const fp16* xr = xin + (size_t)r * CDIM;
    int tid = threadIdx.x;
    float v0 = __half2float(xr[tid]);
    float v1 = __half2float(xr[tid + 128]);
    float v2 = __half2float(xr[tid + 256]);
    float s = v0 + v1 + v2, ss = v0 * v0 + v1 * v1 + v2 * v2;
    #pragma unroll
    for (int o = 16; o; o >>= 1) {
        s  += __shfl_xor_sync(0xffffffffu, s,  o);
        ss += __shfl_xor_sync(0xffffffffu, ss, o);
    }
    __shared__ float rs[4], rss[4], smean, sinv;
    int warp = tid >> 5, lane = tid & 31;
    if (lane == 0) { rs[warp] = s; rss[warp] = ss; }
    __syncthreads();
    if (tid == 0) {
        float S = rs[0] + rs[1] + rs[2] + rs[3];
        float SS = rss[0] + rss[1] + rss[2] + rss[3];
        float m = S * (1.0f / 384.0f);
        smean = m;
        sinv = rsqrtf(SS * (1.0f / 384.0f) - m * m + 1e-5f);
    }
    __syncthreads();
    size_t orow = (size_t)r * CDIM;
    #pragma unroll
    for (int c = 0; c < 3; ++c) {
        float vv = (c == 0 ? v0 : c == 1 ? v1 : v2);
        int col = tid + c * 128;
        oh[orow + col] = __float2half_rn((vv - smean) * sinv * g[col] + bb[col]);
    }
}

// ============================================================
// Big fp16 GEMM (fc2 only now): 128x128, KC=64, 3-stage
// ============================================================
enum { EPI_Q = 0, EPI_PROJ = 1, EPI_GELU = 2, EPI_FC2 = 3 };
#define TILE_B   18432
#define STAGE_B  36864
#define NSTAGE   3
#define SMEM_DYN (NSTAGE * STAGE_B)   // 110592

template <int EPI>
__global__ void __launch_bounds__(256, 2)
mma_gemm(const fp16* __restrict__ Am, const fp16* __restrict__ Bm,
         int K, const float* __restrict__ bias,
         float* __restrict__ Cf, fp16* __restrict__ Ch,
         const float* __restrict__ resid, const fp16* __restrict__ residh,
         float scale)
{
    extern __shared__ char sm_raw[];
    unsigned sbase = smem_u32(sm_raw);

    int tid = threadIdx.x, wid = tid >> 5, lane = tid & 31;
    int bm = blockIdx.y * 128, bn = blockIdx.x * 128;
    int m0 = (wid & 3) * 32, n0 = (wid >> 2) * 64;

    int rowL[8], chL[8], tileL[8];
    #pragma unroll
    for (int t = 0; t < 8; ++t) {
        int item = tid + t * 256;
        tileL[t] = item >> 10;
        int rem = item & 1023;
        rowL[t] = rem >> 3; chL[t] = rem & 7;
    }

    auto load_stage = [&](int stage, int k0) {
        unsigned db = sbase + stage * STAGE_B;
        #pragma unroll
        for (int t = 0; t < 8; ++t) {
            const fp16* src = (tileL[t] ? Bm : Am)
                + (size_t)((tileL[t] ? bn : bm) + rowL[t]) * K + k0 + chL[t] * 8;
            cp16(db + tileL[t] * TILE_B + rowL[t] * 144 + chL[t] * 16, src);
        }
        CP_COMMIT();
    };

    float acc[2][8][4];
    #pragma unroll
    for (int a = 0; a < 2; ++a)
        #pragma unroll
        for (int b = 0; b < 8; ++b)
            #pragma unroll
            for (int c = 0; c < 4; ++c) acc[a][b][c] = 0.0f;

    int niter = K >> 6;
    load_stage(0, 0);
    load_stage(1, 64);

    unsigned a_base[2], b_base[4];
    #pragma unroll
    for (int mt = 0; mt < 2; ++mt)
        a_base[mt] = (m0 + mt * 16 + (lane & 15)) * 144 + (lane >> 4) * 16;
    #pragma unroll
    for (int nt = 0; nt < 4; ++nt)
        b_base[nt] = TILE_B + (n0 + nt * 16 + (lane & 15)) * 144 + (lane >> 4) * 16;

    int st = 0;
    for (int it = 0; it < niter; ++it) {
        CP_WAIT(1);
        __syncthreads();

        if (it + 2 < niter) {
            int pst = st + 2; if (pst >= 3) pst -= 3;
            load_stage(pst, (it + 2) * 64);
        } else CP_COMMIT();

        unsigned base = sbase + st * STAGE_B;

        #pragma unroll
        for (int kp = 0; kp < 2; ++kp) {
            unsigned koff = kp * 64;
            unsigned ah[2][2][4], bh[2][4][4];
            #pragma unroll
            for (int ks = 0; ks < 2; ++ks)
                #pragma unroll
                for (int mt = 0; mt < 2; ++mt)
                    LDSM4(ah[ks][mt], base + a_base[mt] + koff + ks * 32);
            #pragma unroll
            for (int ks = 0; ks < 2; ++ks)
                #pragma unroll
                for (int nt = 0; nt < 4; ++nt)
                    LDSM4(bh[ks][nt], base + b_base[nt] + koff + ks * 32);

            #pragma unroll
            for (int ks = 0; ks < 2; ++ks)
                #pragma unroll
                for (int nt = 0; nt < 4; ++nt)
                    #pragma unroll
                    for (int mt = 0; mt < 2; ++mt) {
                        MMA_F16(acc[mt][nt * 2 + 0], ah[ks][mt], bh[ks][nt][0], bh[ks][nt][2]);
                        MMA_F16(acc[mt][nt * 2 + 1], ah[ks][mt], bh[ks][nt][1], bh[ks][nt][3]);
                    }
        }
        if (++st >= 3) st = 0;
    }

    int r_in = lane >> 2, c_in = (lane & 3) * 2;
    #pragma unroll
    for (int mt = 0; mt < 2; ++mt) {
        #pragma unroll
        for (int j = 0; j < 8; ++j) {
            int col = bn + n0 + j * 8 + c_in;
            #pragma unroll
            for (int hf = 0; hf < 2; ++hf) {
                int row = bm + m0 + mt * 16 + r_in + hf * 8;
                float v0 = acc[mt][j][hf * 2 + 0];
                float v1 = acc[mt][j][hf * 2 + 1];
                if (EPI == EPI_GELU) {
                    float a0 = v0 + bias[col], a1 = v1 + bias[col + 1];
                    float g0 = 0.5f * a0 * (1.0f + erff(a0 * 0.70710678118654752f));
                    float g1 = 0.5f * a1 * (1.0f + erff(a1 * 0.70710678118654752f));
                    __half2 hp;
                    hp.x = __float2half_rn(g0); hp.y = __float2half_rn(g1);
                    *(__half2*)&Ch[(size_t)row * HIDDEN + col] = hp;
                } else {  // EPI_FC2
                    size_t o = (size_t)row * CDIM + col;
                    __half2 rh = *(const __half2*)&residh[o];
                    *(float2*)&Cf[o] = make_float2(v0 + bias[col] + __low2float(rh),
                                                   v1 + bias[col + 1] + __high2float(rh));
                }
            }
        }
    }
}

// ============================================================
// Small-tile GEMM for K=384 layers (q, proj, fc1): 64x128 tile,
// KC=32, 4-stage, 3 CTAs/SM. ldc for GELU output stride.
// ============================================================
#define S_A_B    5120            // 64 rows * 80B
#define S_STAGE  15360
#define SMEM_S   (4 * S_STAGE)   // 61440

template <int EPI>
__global__ void __launch_bounds__(256, 3)
mma_gemm_s(const fp16* __restrict__ Am, const fp16* __restrict__ Bm,
           const float* __restrict__ bias, fp16* __restrict__ Ch,
           const float* __restrict__ resid, float scale)
{
    extern __shared__ char sm_raw[];
    unsigned sbase = smem_u32(sm_raw);

    int tid = threadIdx.x, wid = tid >> 5, lane = tid & 31;
    int bm = blockIdx.y * 64, bn = blockIdx.x * 128;
    int m0 = (wid & 1) * 32, n0 = (wid >> 1) * 32;

    const int K = 384;

    auto load_stage = [&](int stage, int k0) {
        unsigned db = sbase + stage * S_STAGE;
        #pragma unroll
        for (int t = 0; t < 3; ++t) {
            int item = tid + t * 256;
            int isB = item >= 256;
            int rem = isB ? item - 256 : item;
            int row = rem >> 2, ch = rem & 3;
            const fp16* src = (isB ? Bm : Am)
                + (size_t)((isB ? bn : bm) + row) * K + k0 + ch * 8;
            cp16(db + isB * S_A_B + row * 80 + ch * 16, src);
        }
        CP_COMMIT();
    };

    float acc[2][4][4];
    #pragma unroll
    for (int a = 0; a < 2; ++a)
        #pragma unroll
        for (int b = 0; b < 4; ++b)
            #pragma unroll
            for (int c = 0; c < 4; ++c) acc[a][b][c] = 0.0f;

    const int niter = 12;
    load_stage(0, 0);
    load_stage(1, 32);
    load_stage(2, 64);

    unsigned a_base[2], b_base[2];
    #pragma unroll
    for (int mt = 0; mt < 2; ++mt)
        a_base[mt] = (m0 + mt * 16 + (lane & 15)) * 80 + (lane >> 4) * 16;
    #pragma unroll
    for (int nt = 0; nt < 2; ++nt)
        b_base[nt] = S_A_B + (n0 + nt * 16 + (lane & 15)) * 80 + (lane >> 4) * 16;

    for (int it = 0; it < niter; ++it) {
        CP_WAIT(2);
        __syncthreads();

        if (it + 3 < niter) load_stage((it + 3) & 3, (it + 3) * 32);
        else CP_COMMIT();

        unsigned base = sbase + (it & 3) * S_STAGE;

        unsigned ah[2][2][4], bh[2][2][4];
        #pragma unroll
        for (int ks = 0; ks < 2; ++ks) {
            #pragma unroll
            for (int mt = 0; mt < 2; ++mt) LDSM4(ah[ks][mt], base + a_base[mt] + ks * 32);
            #pragma unroll
            for (int nt = 0; nt < 2; ++nt) LDSM4(bh[ks][nt], base + b_base[nt] + ks * 32);
        }
        #pragma unroll
        for (int ks = 0; ks < 2; ++ks)
            #pragma unroll
            for (int nt = 0; nt < 2; ++nt)
                #pragma unroll
                for (int mt = 0; mt < 2; ++mt) {
                    MMA_F16(acc[mt][nt * 2 + 0], ah[ks][mt], bh[ks][nt][0], bh[ks][nt][2]);
                    MMA_F16(acc[mt][nt * 2 + 1], ah[ks][mt], bh[ks][nt][1], bh[ks][nt][3]);
                }
    }

    int r_in = lane >> 2, c_in = (lane & 3) * 2;
    #pragma unroll
    for (int mt = 0; mt < 2; ++mt) {
        #pragma unroll
        for (int j = 0; j < 4; ++j) {
            int col = bn + n0 + j * 8 + c_in;
            #pragma unroll
            for (int hf = 0; hf < 2; ++hf) {
                int row = bm + m0 + mt * 16 + r_in + hf * 8;
                float v0 = acc[mt][j][hf * 2 + 0];
                float v1 = acc[mt][j][hf * 2 + 1];
                if (EPI == EPI_Q) {
                    int w = row / NWIN, n = row % NWIN;
                    int hd = col >> 5, d = col & 31;
                    __half2 hp;
                    hp.x = __float2half_rn((v0 + bias[col]) * scale);
                    hp.y = __float2half_rn((v1 + bias[col + 1]) * scale);
                    *(__half2*)&Ch[((size_t)(w * NHEADS + hd) * NWIN + n) * HDIM + d] = hp;
                } else if (EPI == EPI_PROJ) {
                    int w = row / NWIN, n = row % NWIN;
                    int bimg = w >> 6, wy = (w >> 3) & 7, wx = w & 7;
                    int iy = n / 7, ix = n % 7;
                    size_t o = ((size_t)bimg * 3136 + (wy * 7 + iy) * 56 + (wx * 7 + ix)) * CDIM + col;
                    float2 r2 = *(const float2*)&resid[o];
                    __half2 hp;
                    hp.x = __float2half_rn(v0 + bias[col] + r2.x);
                    hp.y = __float2half_rn(v1 + bias[col + 1] + r2.y);
                    *(__half2*)&Ch[o] = hp;
                } else {  // EPI_GELU (fc1: output stride HIDDEN)
                    float a0 = v0 + bias[col], a1 = v1 + bias[col + 1];
                    float g0 = 0.5f * a0 * (1.0f + erff(a0 * 0.70710678118654752f));
                    float g1 = 0.5f * a1 * (1.0f + erff(a1 * 0.70710678118654752f));
                    __half2 hp;
                    hp.x = __float2half_rn(g0); hp.y = __float2half_rn(g1);
                    *(__half2*)&Ch[(size_t)row * HIDDEN + col] = hp;
                }
            }
        }
    }
}

// ============================================================
// Tensor-core windowed attention (R12-exact)
// ============================================================
#define QK_PITCH 40

__global__ void __launch_bounds__(128)
attn_tc(const fp16* __restrict__ q, const fp16* __restrict__ kvh,
        const fp16* __restrict__ bmh, fp16* __restrict__ ao)
{
    __shared__ fp16 sq[64 * QK_PITCH];
    __shared__ fp16 sk[64 * QK_PITCH];
    __shared__ fp16 sv[64 * QK_PITCH];

    int blk = blockIdx.x;
    int w = blk / NHEADS, h = blk - w * NHEADS;
    int bimg = w >> 6;
    int tid = threadIdx.x, wid = tid >> 5, lane = tid & 31;

    const fp16* qp = q + (size_t)blk * (NWIN * HDIM);
    const fp16* kp = kvh + (size_t)(bimg * NHEADS + h) * (NWIN * HDIM);
    const fp16* vp = kp + (size_t)16 * NHEADS * NWIN * HDIM;

    for (int t = tid; t < 196; t += 128) {
        int row = t >> 2, col = (t & 3) * 8;
        *(uint4*)&sq[row * QK_PITCH + col] = ((const uint4*)qp)[t];
        *(uint4*)&sk[row * QK_PITCH + col] = ((const uint4*)kp)[t];
        *(uint4*)&sv[row * QK_PITCH + col] = ((const uint4*)vp)[t];
    }
    for (int t = tid; t < 60; t += 128) {
        int row = 49 + (t >> 2), col = (t & 3) * 8;
        *(uint4*)&sv[row * QK_PITCH + col] = make_uint4(0, 0, 0, 0);
    }
    __syncthreads();

    unsigned sq_u = smem_u32(sq), sk_u = smem_u32(sk), sv_u = smem_u32(sv);
    int m0 = wid * 16;

    float acc[8][4];
    #pragma unroll
    for (int a = 0; a < 8; ++a)
        #pragma unroll
        for (int c = 0; c < 4; ++c) acc[a][c] = 0.0f;
    {
        unsigned ah[2][4], bh[2][4][4];
        #pragma unroll
        for (int kt = 0; kt < 2; ++kt)
            LDSM4(ah[kt], sq_u + ((m0 + (lane & 15)) * QK_PITCH + kt * 16 + (lane >> 4) * 8) * 2);
        #pragma unroll
        for (int kt = 0; kt < 2; ++kt)
            #pragma unroll
            for (int nt = 0; nt < 4; ++nt)
                LDSM4(bh[kt][nt], sk_u + ((nt * 16 + (lane & 15)) * QK_PITCH + kt * 16 + (lane >> 4) * 8) * 2);
        #pragma unroll
        for (int kt = 0; kt < 2; ++kt)
            #pragma unroll
            for (int nt = 0; nt < 4; ++nt) {
                MMA_F16(acc[nt * 2 + 0], ah[kt], bh[kt][nt][0], bh[kt][nt][2]);
                MMA_F16(acc[nt * 2 + 1], ah[kt], bh[kt][nt][1], bh[kt][nt][3]);
            }
    }

    int r = lane >> 2, c2 = (lane & 3) * 2;
    int i1 = m0 + r, i2 = i1 + 8;
    const fp16* bp = bmh + h * 2500;
    float v1[16], v2[16];
    #pragma unroll
    for (int nj = 0; nj < 8; ++nj) {
        int j0 = nj * 8 + c2;
        float b0 = 0.f, b1 = 0.f, b2 = 0.f, b3 = 0.f;
        if (j0 < 49) {
            if (i1 < 49) {
                __half2 bb = *(const __half2*)&bp[i1 * 50 + j0];
                b0 = __low2float(bb); b1 = __high2float(bb);
            }
            if (i2 < 49) {
                __half2 bb = *(const __half2*)&bp[i2 * 50 + j0];
                b2 = __low2float(bb); b3 = __high2float(bb);
            }
        }
        v1[nj * 2 + 0] = (j0     < 49) ? acc[nj][0] + b0 : -1e30f;
        v1[nj * 2 + 1] = (j0 + 1 < 49) ? acc[nj][1] + b1 : -1e30f;
        v2[nj * 2 + 0] = (j0     < 49) ? acc[nj][2] + b2 : -1e30f;
        v2[nj * 2 + 1] = (j0 + 1 < 49) ? acc[nj][3] + b3 : -1e30f;
    }
    float m1 = -1e30f, m2 = -1e30f;
    #pragma unroll
    for (int t = 0; t < 16; ++t) { m1 = fmaxf(m1, v1[t]); m2 = fmaxf(m2, v2[t]); }
    m1 = fmaxf(m1, __shfl_xor_sync(0xffffffffu, m1, 1));
    m1 = fmaxf(m1, __shfl_xor_sync(0xffffffffu, m1, 2));
    m2 = fmaxf(m2, __shfl_xor_sync(0xffffffffu, m2, 1));
    m2 = fmaxf(m2, __shfl_xor_sync(0xffffffffu, m2, 2));
    float s1 = 0.f, s2 = 0.f;
    #pragma unroll
    for (int t = 0; t < 16; ++t) {
        v1[t] = __expf(v1[t] - m1); s1 += v1[t];
        v2[t] = __expf(v2[t] - m2); s2 += v2[t];
    }
    s1 += __shfl_xor_sync(0xffffffffu, s1, 1);
    s1 += __shfl_xor_sync(0xffffffffu, s1, 2);
    s2 += __shfl_xor_sync(0xffffffffu, s2, 1);
    s2 += __shfl_xor_sync(0xffffffffu, s2, 2);
    float inv1 = 1.0f / s1, inv2 = 1.0f / s2;

    unsigned pa[4][4];
    #pragma unroll
    for (int kt = 0; kt < 4; ++kt) {
        __half2 t0 = __floats2half2_rn(v1[4 * kt + 0] * inv1, v1[4 * kt + 1] * inv1);
        __half2 t1 = __floats2half2_rn(v2[4 * kt + 0] * inv2, v2[4 * kt + 1] * inv2);
        __half2 t2 = __floats2half2_rn(v1[4 * kt + 2] * inv1, v1[4 * kt + 3] * inv1);
        __half2 t3 = __floats2half2_rn(v2[4 * kt + 2] * inv2, v2[4 * kt + 3] * inv2);
        pa[kt][0] = *(unsigned*)&t0;
        pa[kt][1] = *(unsigned*)&t1;
        pa[kt][2] = *(unsigned*)&t2;
        pa[kt][3] = *(unsigned*)&t3;
    }

    float oa[4][4];
    #pragma unroll
    for (int a = 0; a < 4; ++a)
        #pragma unroll
        for (int c = 0; c < 4; ++c) oa[a][c] = 0.0f;
    #pragma unroll
    for (int kt = 0; kt < 4; ++kt) {
        #pragma unroll
        for (int nt = 0; nt < 2; ++nt) {
            unsigned bh2[4];
            LDSM4T(bh2, sv_u + ((kt * 16 + (lane & 15)) * QK_PITCH + nt * 16 + (lane >> 4) * 8) * 2);
            MMA_F16(oa[nt * 2 + 0], pa[kt], bh2[0], bh2[1]);
            MMA_F16(oa[nt * 2 + 1], pa[kt], bh2[2], bh2[3]);
        }
    }
    #pragma unroll
    for (int nt = 0; nt < 4; ++nt) {
        int d = nt * 8 + c2;
        if (i1 < NWIN) {
            __half2 hp;
            hp.x = __float2half_rn(oa[nt][0]); hp.y = __float2half_rn(oa[nt][1]);
            *(__half2*)&ao[((size_t)w * NWIN + i1) * CDIM + h * HDIM + d] = hp;
        }
        if (i2 < NWIN) {
            __half2 hp;
            hp.x = __float2half_rn(oa[nt][2]); hp.y = __float2half_rn(oa[nt][3]);
            *(__half2*)&ao[((size_t)w * NWIN + i2) * CDIM + h * HDIM + d] = hp;
        }
    }
}

// ============================================================
// launch
// ============================================================
extern "C" void kernel_launch(void* const* d_in, const int* in_sizes, int n_in,
                              void* d_out, int out_size)
{
    (void)in_sizes; (void)n_in; (void)out_size;
    const float* x     = (const float*)d_in[0];
    const float* kv    = (const float*)d_in[1];
    const int*   rel   = (const int*)d_in[2];
    const float* g1    = (const float*)d_in[5];
    const float* b1    = (const float*)d_in[6];
    const float* Wqkv  = (const float*)d_in[7];
    const float* bqkv  = (const float*)d_in[8];
    const float* btab  = (const float*)d_in[9];
    const float* Wproj = (const float*)d_in[10];
    const float* bproj = (const float*)d_in[11];
    const float* g2    = (const float*)d_in[12];
    const float* b2    = (const float*)d_in[13];
    const float* Wfc1  = (const float*)d_in[14];
    const float* bfc1  = (const float*)d_in[15];
    const float* Wfc2  = (const float*)d_in[16];
    const float* bfc2  = (const float*)d_in[17];
    float* out = (float*)d_out;

    static fp16 *x1h = nullptr;
    static fp16 *hw, *qh, *ao, *h2, *mid, *wq, *wp, *w1, *w2, *kvh, *bmh;
    if (!x1h) {
        cudaGetSymbolAddress((void**)&x1h, g_x1h);
        cudaGetSymbolAddress((void**)&bmh, g_bmh);
        cudaGetSymbolAddress((void**)&hw,  g_hw);
        cudaGetSymbolAddress((void**)&qh,  g_qh);
        cudaGetSymbolAddress((void**)&ao,  g_ao);
        cudaGetSymbolAddress((void**)&h2,  g_h2);
        cudaGetSymbolAddress((void**)&mid, g_mid);
        cudaGetSymbolAddress((void**)&wq,  g_wq);
        cudaGetSymbolAddress((void**)&wp,  g_wp);
        cudaGetSymbolAddress((void**)&w1,  g_w1);
        cudaGetSymbolAddress((void**)&w2,  g_w2);
        cudaGetSymbolAddress((void**)&kvh, g_kvh);
        cudaFuncSetAttribute(mma_gemm<EPI_FC2>,  cudaFuncAttributeMaxDynamicSharedMemorySize, SMEM_DYN);
        cudaFuncSetAttribute(mma_gemm_s<EPI_Q>,    cudaFuncAttributeMaxDynamicSharedMemorySize, SMEM_S);
        cudaFuncSetAttribute(mma_gemm_s<EPI_PROJ>, cudaFuncAttributeMaxDynamicSharedMemorySize, SMEM_S);
        cudaFuncSetAttribute(mma_gemm_s<EPI_GELU>, cudaFuncAttributeMaxDynamicSharedMemorySize, SMEM_S);
    }

    const float qscale = 0.17677669529663687f;

    pre_kernel<<<PRE_GRID, 128>>>(x, g1, b1, hw,
                                  Wqkv, Wproj, Wfc1, Wfc2, kv, rel, btab,
                                  wq, wp, w1, w2, kvh, bmh);

    mma_gemm_s<EPI_Q><<<dim3(3, 784), 256, SMEM_S>>>(hw, wq,
        bqkv, qh, nullptr, qscale);

    attn_tc<<<BWIN * NHEADS, 128>>>(qh, kvh, bmh, ao);

    mma_gemm_s<EPI_PROJ><<<dim3(3, 784), 256, SMEM_S>>>(ao, wp,
        bproj, x1h, x, 0.0f);

    ln_kernel_h<<<MROWS, 128>>>(x1h, g2, b2, h2);

    // fc1 (K=384) on the small-tile kernel: grid 12x784
    mma_gemm_s<EPI_GELU><<<dim3(12, 784), 256, SMEM_S>>>(h2, w1,
        bfc1, mid, nullptr, 0.0f);

    mma_gemm<EPI_FC2><<<dim3(3, 392), 256, SMEM_DYN>>>(mid, w2, 1536,
        bfc2, out, nullptr, nullptr, x1h, 0.0f);
}